// round 1
// baseline (speedup 1.0000x reference)
#include <cuda_runtime.h>
#include <cuda_bf16.h>

// Problem constants
#define BB   32
#define DD   256
#define NN   2304      // 48*48, H*W
#define HEADS 8
#define HD   32
#define FB   1153      // NN/2+1
#define HF   (HEADS*FB)        // 9224
#define OUT2 (HEADS*FB*2)      // 18448

// ---------------- scratch (no allocations allowed) ----------------
__device__ float g_xnorm[BB*NN*DD];   // [b][n][d]
__device__ float g_xh   [BB*DD*NN];   // [b][d][n]  (column-major for FFT)
__device__ float g_yt   [BB*DD*NN];   // filtered output, [b][d][n]
__device__ float g_ctx  [BB*DD];
__device__ float g_hmid [BB*DD];
__device__ float g_filt [BB*HF];
__device__ float g_bias [BB*HF];
__device__ float g_twc  [NN];
__device__ float g_tws  [NN];

// ---------------- twiddle init ----------------
__global__ void init_tw_kernel() {
    int j = blockIdx.x * blockDim.x + threadIdx.x;
    if (j < NN) {
        float a = (float)j / 1152.0f;      // angle = pi * j/1152 = 2*pi*j/2304
        g_twc[j] = cospif(a);
        g_tws[j] = sinpif(a);
    }
}

// ---------------- LayerNorm ----------------
__global__ void ln_kernel(const float* __restrict__ x,
                          const float* __restrict__ gamma,
                          const float* __restrict__ beta) {
    __shared__ float sred[8];
    long row = blockIdx.x;                 // b*NN + n
    int t = threadIdx.x;                   // d
    float v = x[row * DD + t];

    // mean
    float s = v;
    #pragma unroll
    for (int o = 16; o; o >>= 1) s += __shfl_xor_sync(0xffffffffu, s, o);
    if ((t & 31) == 0) sred[t >> 5] = s;
    __syncthreads();
    if (t < 32) {
        float z = (t < 8) ? sred[t] : 0.f;
        #pragma unroll
        for (int o = 4; o; o >>= 1) z += __shfl_xor_sync(0xffffffffu, z, o);
        if (t == 0) sred[0] = z;
    }
    __syncthreads();
    float mu = sred[0] * (1.0f / DD);
    __syncthreads();

    // var
    float dv = v - mu;
    float s2 = dv * dv;
    #pragma unroll
    for (int o = 16; o; o >>= 1) s2 += __shfl_xor_sync(0xffffffffu, s2, o);
    if ((t & 31) == 0) sred[t >> 5] = s2;
    __syncthreads();
    if (t < 32) {
        float z = (t < 8) ? sred[t] : 0.f;
        #pragma unroll
        for (int o = 4; o; o >>= 1) z += __shfl_xor_sync(0xffffffffu, z, o);
        if (t == 0) sred[0] = z;
    }
    __syncthreads();
    float var = sred[0] * (1.0f / DD);

    g_xnorm[row * DD + t] = dv * rsqrtf(var + 1e-5f) * gamma[t] + beta[t];
}

// ---------------- transpose [b][n][d] -> [b][d][n] ----------------
__global__ void transpose_kernel() {
    __shared__ float tile[32][33];
    int b  = blockIdx.z;
    int n0 = blockIdx.x * 32;
    int d0 = blockIdx.y * 32;
    int tx = threadIdx.x, ty = threadIdx.y;      // (32,8)
    const float* src = g_xnorm + ((long)b * NN + n0) * DD + d0;
    #pragma unroll
    for (int i = 0; i < 32; i += 8)
        tile[ty + i][tx] = src[(long)(ty + i) * DD + tx];   // tile[n][d]
    __syncthreads();
    float* dst = g_xh + ((long)b * DD + d0) * NN + n0;
    #pragma unroll
    for (int i = 0; i < 32; i += 8)
        dst[(long)(ty + i) * NN + tx] = tile[tx][ty + i];   // out[d][n]
}

// ---------------- context = mean over n ----------------
__global__ void ctx_kernel() {
    int idx  = blockIdx.x * 8 + (threadIdx.x >> 5);  // b*DD + d, 8192 total
    int lane = threadIdx.x & 31;
    const float* p = g_xh + (long)idx * NN;
    float s = 0.f;
    for (int n = lane; n < NN; n += 32) s += p[n];
    #pragma unroll
    for (int o = 16; o; o >>= 1) s += __shfl_xor_sync(0xffffffffu, s, o);
    if (lane == 0) g_ctx[idx] = s * (1.0f / NN);
}

// ---------------- MLP layer 1: gelu(ctx @ W1 + b1) ----------------
__global__ void mlp1_kernel(const float* __restrict__ W1, const float* __restrict__ b1) {
    __shared__ float sc[DD];
    int b = blockIdx.x, t = threadIdx.x;
    sc[t] = g_ctx[b * DD + t];
    __syncthreads();
    float acc = b1[t];
    #pragma unroll 8
    for (int d = 0; d < DD; d++) acc += sc[d] * W1[d * DD + t];
    g_hmid[b * DD + t] = 0.5f * acc * (1.0f + erff(acc * 0.70710678118654752f));
}

// ---------------- MLP layer 2 -> filter/bias ----------------
__global__ void mlp2_kernel(const float* __restrict__ W2, const float* __restrict__ b2,
                            const float* __restrict__ base_filter,
                            const float* __restrict__ base_bias) {
    __shared__ float sh[DD];
    int b = blockIdx.y, t = threadIdx.x;
    sh[t] = g_hmid[b * DD + t];
    __syncthreads();
    int o = blockIdx.x * 256 + t;
    if (o >= OUT2) return;
    float acc = b2[o];
    #pragma unroll 8
    for (int j = 0; j < DD; j++) acc += sh[j] * W2[(long)j * OUT2 + o];
    int idx2 = o >> 1;                      // h*FB + f
    if ((o & 1) == 0)
        g_filt[(long)b * HF + idx2] = base_filter[idx2] * (1.0f + acc);
    else
        g_bias[(long)b * HF + idx2] = base_bias[idx2] + acc;
}

// ---------------- spectral kernel: fwd FFT, modulate, inv FFT ----------------
// One block per column (b, d=h*32+e). Cooley-Tukey 48x48.
__global__ __launch_bounds__(256) void spectral_kernel() {
    __shared__ float sx[NN];
    __shared__ float wr[48 * 49], wi[48 * 49];
    __shared__ float Xr[NN], Xi[NN];
    __shared__ float c48[48], s48[48];

    int col = blockIdx.x;          // b*256 + d
    int b = col >> 8;
    int d = col & 255;
    int h = d >> 5;
    int t = threadIdx.x;

    const float* src = g_xh + (long)col * NN;
    for (int i = t; i < NN; i += 256) sx[i] = src[i];
    if (t < 48) { c48[t] = g_twc[t * 48]; s48[t] = g_tws[t * 48]; }
    __syncthreads();

    // ---- forward stage 1 (real 48-pt DFTs over n1) + twiddle W^(n2*k1) ----
    for (int o = t; o < NN; o += 256) {
        int k1 = o / 48, n2 = o - k1 * 48;
        float ar = 0.f, ai = 0.f;
        int idx = 0;
        #pragma unroll 8
        for (int n1 = 0; n1 < 48; n1++) {
            float c = c48[idx], s = s48[idx];
            idx += k1; if (idx >= 48) idx -= 48;
            float v = sx[n1 * 48 + n2];
            ar += v * c;
            ai -= v * s;
        }
        int j = n2 * k1;                         // < 2304
        float tc = g_twc[j], ts = g_tws[j];
        wr[n2 * 49 + k1] = ar * tc + ai * ts;    // * e^{-i theta}
        wi[n2 * 49 + k1] = ai * tc - ar * ts;
    }
    __syncthreads();

    // ---- forward stage 2 (complex 48-pt DFTs over n2) + scale + modulation ----
    const float inv48 = 1.0f / 48.0f;
    const float* fB = g_filt + (long)b * HF + (long)h * FB;
    const float* cB = g_bias + (long)b * HF + (long)h * FB;
    for (int k = t; k < NN; k += 256) {
        int k2 = k / 48, k1 = k - k2 * 48;
        float ar = 0.f, ai = 0.f;
        int idx = 0;
        #pragma unroll 8
        for (int n2 = 0; n2 < 48; n2++) {
            float c = c48[idx], s = s48[idx];
            idx += k2; if (idx >= 48) idx -= 48;
            float br = wr[n2 * 49 + k1], bi = wi[n2 * 49 + k1];
            ar += br * c + bi * s;               // * e^{-i theta}
            ai += bi * c - br * s;
        }
        float Fr = ar * inv48, Fi = ai * inv48;  // ortho-normalized rfft value
        int f = (k <= 1152) ? k : (NN - k);      // Hermitian mirror
        float g  = fB[f];
        float cc = cB[f];
        float mr = Fr * g + cc;
        float mi = Fi * g;
        float mag = sqrtf(mr * mr + mi * mi);
        float gel = 0.5f * mag * (1.0f + erff(mag * 0.70710678118654752f));
        float fac = gel / (mag + 1e-6f);
        Xr[k] = mr * fac;
        Xi[k] = mi * fac;
    }
    __syncthreads();

    // ---- inverse stage 1 (complex 48-pt inverse DFTs over k2) + twiddle e^{+i 2pi r k1/N} ----
    for (int o = t; o < NN; o += 256) {
        int r = o / 48, k1 = o - r * 48;
        float gr = 0.f, gi = 0.f;
        int idx = 0;
        #pragma unroll 8
        for (int k2 = 0; k2 < 48; k2++) {
            float c = c48[idx], s = s48[idx];
            idx += r; if (idx >= 48) idx -= 48;
            float xr = Xr[k1 + 48 * k2], xi = Xi[k1 + 48 * k2];
            gr += xr * c - xi * s;               // * e^{+i theta}
            gi += xr * s + xi * c;
        }
        int j = r * k1;                          // < 2304
        float tc = g_twc[j], ts = g_tws[j];
        wr[r * 49 + k1] = gr * tc - gi * ts;     // * e^{+i theta}
        wi[r * 49 + k1] = gr * ts + gi * tc;
    }
    __syncthreads();

    // ---- inverse stage 2: y[r+48q] = Re( sum_k1 H[k1][r] e^{+i 2pi q k1/48} ) / 48 ----
    float* dst = g_yt + (long)col * NN;
    for (int n = t; n < NN; n += 256) {
        int q = n / 48, r = n - q * 48;
        float acc = 0.f;
        int idx = 0;
        #pragma unroll 8
        for (int k1 = 0; k1 < 48; k1++) {
            float c = c48[idx], s = s48[idx];
            idx += q; if (idx >= 48) idx -= 48;
            acc += wr[r * 49 + k1] * c - wi[r * 49 + k1] * s;
        }
        dst[n] = acc * inv48;
    }
}

// ---------------- output: out[b][n][d] = x[b][n][d] + yt[b][d][n] ----------------
__global__ void addout_kernel(const float* __restrict__ x, float* __restrict__ out) {
    __shared__ float tile[32][33];
    int b  = blockIdx.z;
    int n0 = blockIdx.x * 32;
    int d0 = blockIdx.y * 32;
    int tx = threadIdx.x, ty = threadIdx.y;      // (32,8)
    const float* src = g_yt + ((long)b * DD + d0) * NN + n0;
    #pragma unroll
    for (int i = 0; i < 32; i += 8)
        tile[ty + i][tx] = src[(long)(ty + i) * NN + tx];   // tile[d][n]
    __syncthreads();
    long base = ((long)b * NN + n0) * DD + d0;
    #pragma unroll
    for (int i = 0; i < 32; i += 8)
        out[base + (long)(ty + i) * DD + tx] =
            x[base + (long)(ty + i) * DD + tx] + tile[tx][ty + i];
}

// ---------------- launch ----------------
extern "C" void kernel_launch(void* const* d_in, const int* in_sizes, int n_in,
                              void* d_out, int out_size) {
    const float* x           = (const float*)d_in[0];
    const float* base_filter = (const float*)d_in[1];
    const float* base_bias   = (const float*)d_in[2];
    const float* ln_gamma    = (const float*)d_in[3];
    const float* ln_beta     = (const float*)d_in[4];
    const float* W1          = (const float*)d_in[5];
    const float* b1          = (const float*)d_in[6];
    const float* W2          = (const float*)d_in[7];
    const float* b2          = (const float*)d_in[8];
    float* out = (float*)d_out;

    init_tw_kernel<<<(NN + 255) / 256, 256>>>();
    ln_kernel<<<BB * NN, 256>>>(x, ln_gamma, ln_beta);
    transpose_kernel<<<dim3(NN / 32, DD / 32, BB), dim3(32, 8)>>>();
    ctx_kernel<<<(BB * DD) / 8, 256>>>();
    mlp1_kernel<<<BB, 256>>>(W1, b1);
    mlp2_kernel<<<dim3((OUT2 + 255) / 256, BB), 256>>>(W2, b2, base_filter, base_bias);
    spectral_kernel<<<BB * DD, 256>>>();
    addout_kernel<<<dim3(NN / 32, DD / 32, BB), dim3(32, 8)>>>(x, out);
}

// round 2
// speedup vs baseline: 2.2270x; 2.2270x over previous
#include <cuda_runtime.h>
#include <cuda_bf16.h>

// Problem constants
#define BB   32
#define DD   256
#define NN   2304      // 48*48
#define HEADS 8
#define FB   1153      // NN/2+1
#define HF   (HEADS*FB)        // 9224
#define OUT2 (HEADS*FB*2)      // 18448

#define SPEC_SMEM (14592*4)    // bytes of dynamic smem for spectral kernel

// ---------------- scratch ----------------
__device__ float g_xh  [BB*DD*NN];   // [b][d][n]
__device__ float g_yt  [BB*DD*NN];   // filtered, [b][d][n]
__device__ float g_ctx [BB*DD];
__device__ float g_hmid[BB*DD];
__device__ float g_filt[BB*HF];
__device__ float g_bias[BB*HF];

// ---------------- fused LayerNorm + transpose ----------------
// block: 256 thr, handles 32 rows (n) x 256 (d); writes [b][d][n]
__global__ __launch_bounds__(256) void ln_t_kernel(const float* __restrict__ x,
                                                   const float* __restrict__ gamma,
                                                   const float* __restrict__ beta) {
    __shared__ float tile[32 * 257];
    __shared__ float smu[32], srs[32];
    int b  = blockIdx.y;
    int n0 = blockIdx.x * 32;
    int t  = threadIdx.x;

    const float* src = x + ((long)b * NN + n0) * DD;
    #pragma unroll
    for (int l = t; l < 32 * DD; l += 256) {
        int r = l >> 8, d = l & 255;
        tile[r * 257 + d] = src[l];
    }
    __syncthreads();

    int w = t >> 5, lane = t & 31;
    #pragma unroll
    for (int r = w; r < 32; r += 8) {
        float s = 0.f, s2 = 0.f;
        #pragma unroll
        for (int j = 0; j < 8; j++) {
            float v = tile[r * 257 + lane + j * 32];
            s += v; s2 += v * v;
        }
        #pragma unroll
        for (int o = 16; o; o >>= 1) {
            s  += __shfl_xor_sync(0xffffffffu, s, o);
            s2 += __shfl_xor_sync(0xffffffffu, s2, o);
        }
        if (lane == 0) {
            float mu = s * (1.0f / 256.0f);
            smu[r] = mu;
            srs[r] = rsqrtf(s2 * (1.0f / 256.0f) - mu * mu + 1e-5f);
        }
    }
    __syncthreads();

    #pragma unroll
    for (int l = t; l < 32 * DD; l += 256) {
        int d = l >> 5, i = l & 31;
        float v = (tile[i * 257 + d] - smu[i]) * srs[i] * gamma[d] + beta[d];
        g_xh[((long)b * DD + d) * NN + n0 + i] = v;
    }
}

// ---------------- context = mean over n ----------------
__global__ void ctx_kernel() {
    int idx  = blockIdx.x * 8 + (threadIdx.x >> 5);
    int lane = threadIdx.x & 31;
    const float* p = g_xh + (long)idx * NN;
    float s = 0.f;
    for (int n = lane; n < NN; n += 32) s += p[n];
    #pragma unroll
    for (int o = 16; o; o >>= 1) s += __shfl_xor_sync(0xffffffffu, s, o);
    if (lane == 0) g_ctx[idx] = s * (1.0f / NN);
}

// ---------------- MLP layer 1 ----------------
__global__ void mlp1_kernel(const float* __restrict__ W1, const float* __restrict__ b1) {
    __shared__ float sc[DD];
    int b = blockIdx.x, t = threadIdx.x;
    sc[t] = g_ctx[b * DD + t];
    __syncthreads();
    float acc = b1[t];
    #pragma unroll 8
    for (int d = 0; d < DD; d++) acc += sc[d] * W1[d * DD + t];
    g_hmid[b * DD + t] = 0.5f * acc * (1.0f + erff(acc * 0.70710678118654752f));
}

// ---------------- MLP layer 2 -> filter/bias ----------------
__global__ void mlp2_kernel(const float* __restrict__ W2, const float* __restrict__ b2,
                            const float* __restrict__ base_filter,
                            const float* __restrict__ base_bias) {
    __shared__ float sh[DD];
    int b = blockIdx.y, t = threadIdx.x;
    sh[t] = g_hmid[b * DD + t];
    __syncthreads();
    int o = blockIdx.x * 256 + t;
    if (o >= OUT2) return;
    float acc = b2[o];
    #pragma unroll 8
    for (int j = 0; j < DD; j++) acc += sh[j] * W2[(long)j * OUT2 + o];
    int idx2 = o >> 1;
    if ((o & 1) == 0)
        g_filt[(long)b * HF + idx2] = base_filter[idx2] * (1.0f + acc);
    else
        g_bias[(long)b * HF + idx2] = base_bias[idx2] + acc;
}

// ---------------- spectral kernel ----------------
// One block per (b,d) column. 288 threads, 8 outputs each.
// Twiddle table stc/sts[a*48+b] = cos/sin(2*pi*a*b/48)  (symmetric!)
// Data arrays padded to stride 52 (16B-aligned rows, conflict-free).
__global__ __launch_bounds__(288) void spectral_kernel() {
    extern __shared__ float sm[];
    float* stc  = sm;            // 2304
    float* sts  = sm + 2304;     // 2304
    float* bufA = sm + 4608;     // 2496: sx (2304 used), later Xr[48][52]
    float* Xim  = sm + 7104;     // 2496: Xi[48][52]
    float* wre  = sm + 9600;     // 2496
    float* wim  = sm + 12096;    // 2496

    int col = blockIdx.x;
    int b = col >> 8, d = col & 255, h = d >> 5;
    int t = threadIdx.x;
    int c  = t % 48;             // lane var (k1/k2/r/q per stage)
    int g  = t / 48;             // group 0..5
    int c8 = g * 8;
    const float inv48 = 1.0f / 48.0f;

    // build twiddle table (integer-reduced -> exact-ish)
    for (int i = t; i < 2304; i += 288) {
        int k = i / 48, n = i - k * 48;
        int m = (k * n) % 48;
        float sv, cv;
        sincospif((float)m * (1.0f / 24.0f), &sv, &cv);
        stc[i] = cv; sts[i] = sv;
    }
    const float* src = g_xh + (long)col * NN;
    for (int i = t; i < NN; i += 288) bufA[i] = src[i];
    __syncthreads();

    // ---- stage 1: A[k1][n2] = sum_n1 x[n1*48+n2] e^{-2pi i k1 n1/48}, then * e^{-2pi i k1 n2/N}
    {
        float ar[8], ai[8];
        #pragma unroll
        for (int j = 0; j < 8; j++) { ar[j] = 0.f; ai[j] = 0.f; }
        #pragma unroll 4
        for (int n1 = 0; n1 < 48; n1++) {
            float cv = stc[n1 * 48 + c], sv = sts[n1 * 48 + c];
            float4 v0 = *(const float4*)&bufA[n1 * 48 + c8];
            float4 v1 = *(const float4*)&bufA[n1 * 48 + c8 + 4];
            float v[8] = {v0.x, v0.y, v0.z, v0.w, v1.x, v1.y, v1.z, v1.w};
            #pragma unroll
            for (int j = 0; j < 8; j++) { ar[j] += v[j] * cv; ai[j] -= v[j] * sv; }
        }
        #pragma unroll
        for (int j = 0; j < 8; j++) {
            int n2 = c8 + j;
            float sv, cv;
            sincospif((float)(c * n2) * (1.0f / 1152.0f), &sv, &cv);
            wre[n2 * 52 + c] = ar[j] * cv + ai[j] * sv;
            wim[n2 * 52 + c] = ai[j] * cv - ar[j] * sv;
        }
    }
    __syncthreads();

    // ---- stage 2: F[k2*48+k1] = sum_n2 w[k1][n2] e^{-2pi i k2 n2/48}; scale; modulate
    {
        float zr[8], zi[8];
        #pragma unroll
        for (int j = 0; j < 8; j++) { zr[j] = 0.f; zi[j] = 0.f; }
        #pragma unroll 4
        for (int n2 = 0; n2 < 48; n2++) {
            float cv = stc[n2 * 48 + c], sv = sts[n2 * 48 + c];
            float4 br0 = *(const float4*)&wre[n2 * 52 + c8];
            float4 br1 = *(const float4*)&wre[n2 * 52 + c8 + 4];
            float4 bi0 = *(const float4*)&wim[n2 * 52 + c8];
            float4 bi1 = *(const float4*)&wim[n2 * 52 + c8 + 4];
            float br[8] = {br0.x, br0.y, br0.z, br0.w, br1.x, br1.y, br1.z, br1.w};
            float bi[8] = {bi0.x, bi0.y, bi0.z, bi0.w, bi1.x, bi1.y, bi1.z, bi1.w};
            #pragma unroll
            for (int j = 0; j < 8; j++) {
                zr[j] += br[j] * cv + bi[j] * sv;
                zi[j] += bi[j] * cv - br[j] * sv;
            }
        }
        const float* fB = g_filt + (long)b * HF + (long)h * FB;
        const float* cB = g_bias + (long)b * HF + (long)h * FB;
        float xr8[8], xi8[8];
        #pragma unroll
        for (int j = 0; j < 8; j++) {
            int k = c * 48 + c8 + j;
            int f = (k <= 1152) ? k : (2304 - k);
            float gf = fB[f], bb = cB[f];
            float Fr = zr[j] * inv48, Fi = zi[j] * inv48;
            float mr = Fr * gf + bb;
            float mi = Fi * gf;
            float mag = sqrtf(mr * mr + mi * mi);
            float gel = 0.5f * mag * (1.0f + erff(mag * 0.70710678118654752f));
            float fac = gel / (mag + 1e-6f);
            xr8[j] = mr * fac; xi8[j] = mi * fac;
        }
        __syncthreads();  // bufA (sx) dead -> reuse as Xr
        float4* pr = (float4*)&bufA[c * 52 + c8];
        pr[0] = make_float4(xr8[0], xr8[1], xr8[2], xr8[3]);
        pr[1] = make_float4(xr8[4], xr8[5], xr8[6], xr8[7]);
        float4* pi = (float4*)&Xim[c * 52 + c8];
        pi[0] = make_float4(xi8[0], xi8[1], xi8[2], xi8[3]);
        pi[1] = make_float4(xi8[4], xi8[5], xi8[6], xi8[7]);
    }
    __syncthreads();

    // ---- stage 3: G[k1][r] = sum_k2 X[k2*48+k1] e^{+2pi i r k2/48}, then * e^{+2pi i r k1/N}
    // stored transposed: H[k1][r]
    {
        float gr[8], gi[8];
        #pragma unroll
        for (int j = 0; j < 8; j++) { gr[j] = 0.f; gi[j] = 0.f; }
        #pragma unroll 4
        for (int k2 = 0; k2 < 48; k2++) {
            float cv = stc[k2 * 48 + c], sv = sts[k2 * 48 + c];
            float4 xr0 = *(const float4*)&bufA[k2 * 52 + c8];
            float4 xr1 = *(const float4*)&bufA[k2 * 52 + c8 + 4];
            float4 xi0 = *(const float4*)&Xim[k2 * 52 + c8];
            float4 xi1 = *(const float4*)&Xim[k2 * 52 + c8 + 4];
            float xr[8] = {xr0.x, xr0.y, xr0.z, xr0.w, xr1.x, xr1.y, xr1.z, xr1.w};
            float xi[8] = {xi0.x, xi0.y, xi0.z, xi0.w, xi1.x, xi1.y, xi1.z, xi1.w};
            #pragma unroll
            for (int j = 0; j < 8; j++) {
                gr[j] += xr[j] * cv - xi[j] * sv;
                gi[j] += xr[j] * sv + xi[j] * cv;
            }
        }
        #pragma unroll
        for (int j = 0; j < 8; j++) {
            int k1 = c8 + j;
            float sv, cv;
            sincospif((float)(c * k1) * (1.0f / 1152.0f), &sv, &cv);
            wre[k1 * 52 + c] = gr[j] * cv - gi[j] * sv;
            wim[k1 * 52 + c] = gr[j] * sv + gi[j] * cv;
        }
    }
    __syncthreads();

    // ---- stage 4: y[q*48+r] = Re( sum_k1 H[k1][r] e^{+2pi i q k1/48} ) / 48
    {
        float y[8];
        #pragma unroll
        for (int j = 0; j < 8; j++) y[j] = 0.f;
        #pragma unroll 4
        for (int k1 = 0; k1 < 48; k1++) {
            float cv = stc[k1 * 48 + c], sv = sts[k1 * 48 + c];
            float4 hr0 = *(const float4*)&wre[k1 * 52 + c8];
            float4 hr1 = *(const float4*)&wre[k1 * 52 + c8 + 4];
            float4 hi0 = *(const float4*)&wim[k1 * 52 + c8];
            float4 hi1 = *(const float4*)&wim[k1 * 52 + c8 + 4];
            float hr[8] = {hr0.x, hr0.y, hr0.z, hr0.w, hr1.x, hr1.y, hr1.z, hr1.w};
            float hi[8] = {hi0.x, hi0.y, hi0.z, hi0.w, hi1.x, hi1.y, hi1.z, hi1.w};
            #pragma unroll
            for (int j = 0; j < 8; j++) y[j] += hr[j] * cv - hi[j] * sv;
        }
        float* dst = g_yt + (long)col * NN + c * 48 + c8;
        *(float4*)dst       = make_float4(y[0] * inv48, y[1] * inv48, y[2] * inv48, y[3] * inv48);
        *(float4*)(dst + 4) = make_float4(y[4] * inv48, y[5] * inv48, y[6] * inv48, y[7] * inv48);
    }
}

// ---------------- output: out[b][n][d] = x + yt^T ----------------
__global__ void addout_kernel(const float* __restrict__ x, float* __restrict__ out) {
    __shared__ float tile[32][33];
    int b  = blockIdx.z;
    int n0 = blockIdx.x * 32;
    int d0 = blockIdx.y * 32;
    int tx = threadIdx.x, ty = threadIdx.y;
    const float* src = g_yt + ((long)b * DD + d0) * NN + n0;
    #pragma unroll
    for (int i = 0; i < 32; i += 8)
        tile[ty + i][tx] = src[(long)(ty + i) * NN + tx];
    __syncthreads();
    long base = ((long)b * NN + n0) * DD + d0;
    #pragma unroll
    for (int i = 0; i < 32; i += 8)
        out[base + (long)(ty + i) * DD + tx] =
            x[base + (long)(ty + i) * DD + tx] + tile[tx][ty + i];
}

// ---------------- launch ----------------
extern "C" void kernel_launch(void* const* d_in, const int* in_sizes, int n_in,
                              void* d_out, int out_size) {
    const float* x           = (const float*)d_in[0];
    const float* base_filter = (const float*)d_in[1];
    const float* base_bias   = (const float*)d_in[2];
    const float* ln_gamma    = (const float*)d_in[3];
    const float* ln_beta     = (const float*)d_in[4];
    const float* W1          = (const float*)d_in[5];
    const float* b1          = (const float*)d_in[6];
    const float* W2          = (const float*)d_in[7];
    const float* b2          = (const float*)d_in[8];
    float* out = (float*)d_out;

    static bool attr_done = false;
    if (!attr_done) {
        cudaFuncSetAttribute(spectral_kernel,
                             cudaFuncAttributeMaxDynamicSharedMemorySize, SPEC_SMEM);
        attr_done = true;
    }

    ln_t_kernel<<<dim3(NN / 32, BB), 256>>>(x, ln_gamma, ln_beta);
    ctx_kernel<<<(BB * DD) / 8, 256>>>();
    mlp1_kernel<<<BB, 256>>>(W1, b1);
    mlp2_kernel<<<dim3((OUT2 + 255) / 256, BB), 256>>>(W2, b2, base_filter, base_bias);
    spectral_kernel<<<BB * DD, 288, SPEC_SMEM>>>();
    addout_kernel<<<dim3(NN / 32, DD / 32, BB), dim3(32, 8)>>>(x, out);
}

// round 3
// speedup vs baseline: 2.5562x; 1.1478x over previous
#include <cuda_runtime.h>
#include <cuda_bf16.h>

// Problem constants
#define BB   32
#define DD   256
#define NN   2304      // 48*48
#define HEADS 8
#define FB   1153      // NN/2+1
#define HF   (HEADS*FB)        // 9224
#define OUT2 (HEADS*FB*2)      // 18448

// dynamic smem: float2 twiddle table (2304*8B) + 4 data arrays (2496*4B each)
#define SPEC_SMEM (2304*8 + 4*2496*4)

// ---------------- scratch ----------------
__device__ float  g_xh  [BB*DD*NN];   // [b][d][n]
__device__ float  g_yt  [BB*DD*NN];   // filtered, [b][d][n]
__device__ float  g_ctx [BB*DD];
__device__ float  g_hmid[BB*DD];
__device__ float  g_filt[BB*HF];
__device__ float  g_bias[BB*HF];
__device__ float2 g_tw  [NN];         // (cos, sin)(2*pi*j/2304)

typedef unsigned long long u64;

// ---------------- packed f32x2 helpers ----------------
__device__ __forceinline__ u64 pk2(float lo, float hi) {
    u64 r; asm("mov.b64 %0, {%1,%2};" : "=l"(r) : "f"(lo), "f"(hi)); return r;
}
__device__ __forceinline__ void upk2(u64 v, float& lo, float& hi) {
    asm("mov.b64 {%0,%1}, %2;" : "=f"(lo), "=f"(hi) : "l"(v));
}
__device__ __forceinline__ u64 f2fma(u64 a, u64 b, u64 c) {
    u64 d; asm("fma.rn.f32x2 %0, %1, %2, %3;" : "=l"(d) : "l"(a), "l"(b), "l"(c)); return d;
}

// ---------------- twiddle init ----------------
__global__ void init_tw_kernel() {
    int j = blockIdx.x * blockDim.x + threadIdx.x;
    if (j < NN) {
        float sv, cv;
        sincospif((float)j * (1.0f / 1152.0f), &sv, &cv);
        g_tw[j] = make_float2(cv, sv);
    }
}

// ---------------- fused LayerNorm + transpose ----------------
__global__ __launch_bounds__(256) void ln_t_kernel(const float* __restrict__ x,
                                                   const float* __restrict__ gamma,
                                                   const float* __restrict__ beta) {
    __shared__ float tile[32 * 257];
    __shared__ float smu[32], srs[32];
    int b  = blockIdx.y;
    int n0 = blockIdx.x * 32;
    int t  = threadIdx.x;

    const float* src = x + ((long)b * NN + n0) * DD;
    #pragma unroll
    for (int l = t; l < 32 * DD; l += 256) {
        int r = l >> 8, d = l & 255;
        tile[r * 257 + d] = src[l];
    }
    __syncthreads();

    int w = t >> 5, lane = t & 31;
    #pragma unroll
    for (int r = w; r < 32; r += 8) {
        float s = 0.f, s2 = 0.f;
        #pragma unroll
        for (int j = 0; j < 8; j++) {
            float v = tile[r * 257 + lane + j * 32];
            s += v; s2 += v * v;
        }
        #pragma unroll
        for (int o = 16; o; o >>= 1) {
            s  += __shfl_xor_sync(0xffffffffu, s, o);
            s2 += __shfl_xor_sync(0xffffffffu, s2, o);
        }
        if (lane == 0) {
            float mu = s * (1.0f / 256.0f);
            smu[r] = mu;
            srs[r] = rsqrtf(s2 * (1.0f / 256.0f) - mu * mu + 1e-5f);
        }
    }
    __syncthreads();

    #pragma unroll
    for (int l = t; l < 32 * DD; l += 256) {
        int d = l >> 5, i = l & 31;
        float v = (tile[i * 257 + d] - smu[i]) * srs[i] * gamma[d] + beta[d];
        g_xh[((long)b * DD + d) * NN + n0 + i] = v;
    }
}

// ---------------- context ----------------
__global__ void ctx_kernel() {
    int idx  = blockIdx.x * 8 + (threadIdx.x >> 5);
    int lane = threadIdx.x & 31;
    const float* p = g_xh + (long)idx * NN;
    float s = 0.f;
    for (int n = lane; n < NN; n += 32) s += p[n];
    #pragma unroll
    for (int o = 16; o; o >>= 1) s += __shfl_xor_sync(0xffffffffu, s, o);
    if (lane == 0) g_ctx[idx] = s * (1.0f / NN);
}

// ---------------- MLP layer 1 ----------------
__global__ void mlp1_kernel(const float* __restrict__ W1, const float* __restrict__ b1) {
    __shared__ float sc[DD];
    int b = blockIdx.x, t = threadIdx.x;
    sc[t] = g_ctx[b * DD + t];
    __syncthreads();
    float acc = b1[t];
    #pragma unroll 8
    for (int d = 0; d < DD; d++) acc += sc[d] * W1[d * DD + t];
    g_hmid[b * DD + t] = 0.5f * acc * (1.0f + erff(acc * 0.70710678118654752f));
}

// ---------------- MLP layer 2 ----------------
__global__ void mlp2_kernel(const float* __restrict__ W2, const float* __restrict__ b2,
                            const float* __restrict__ base_filter,
                            const float* __restrict__ base_bias) {
    __shared__ float sh[DD];
    int b = blockIdx.y, t = threadIdx.x;
    sh[t] = g_hmid[b * DD + t];
    __syncthreads();
    int o = blockIdx.x * 256 + t;
    if (o >= OUT2) return;
    float acc = b2[o];
    #pragma unroll 8
    for (int j = 0; j < DD; j++) acc += sh[j] * W2[(long)j * OUT2 + o];
    int idx2 = o >> 1;
    if ((o & 1) == 0)
        g_filt[(long)b * HF + idx2] = base_filter[idx2] * (1.0f + acc);
    else
        g_bias[(long)b * HF + idx2] = base_bias[idx2] + acc;
}

// ---------------- spectral kernel (packed f32x2) ----------------
__global__ __launch_bounds__(288) void spectral_kernel() {
    extern __shared__ float sm[];
    float2* stcs = (float2*)sm;           // [2304] (c,s) pairs
    float*  bufA = sm + 4608;             // 2496: sx / Xr
    float*  Xim  = sm + 7104;             // 2496
    float*  wre  = sm + 9600;             // 2496
    float*  wim  = sm + 12096;            // 2496

    int col = blockIdx.x;
    int b = col >> 8, d = col & 255, h = d >> 5;
    int t = threadIdx.x;
    int c  = t % 48;
    int g  = t / 48;
    int c8 = g * 8;
    const float inv48 = 1.0f / 48.0f;

    // build 48x48 twiddle table from global (exact values, no trig)
    for (int i = t; i < 2304; i += 288) {
        int k = i / 48, n = i - k * 48;
        stcs[i] = g_tw[48 * ((k * n) % 48)];
    }
    const float* src = g_xh + (long)col * NN;
    for (int i = t; i < NN; i += 288) bufA[i] = src[i];
    __syncthreads();

    // ---- stage 1: A[k1][n2] = sum_n1 x[n1*48+n2] e^{-2pi i k1 n1/48}; * e^{-2pi i k1 n2/N}
    {
        u64 ar[4], ai[4];
        #pragma unroll
        for (int j = 0; j < 4; j++) { ar[j] = 0ULL; ai[j] = 0ULL; }
        #pragma unroll 4
        for (int n1 = 0; n1 < 48; n1++) {
            float2 w = stcs[n1 * 48 + c];
            u64 cc = pk2(w.x, w.x), ns = pk2(-w.y, -w.y);
            ulonglong2 v0 = *(const ulonglong2*)&bufA[n1 * 48 + c8];
            ulonglong2 v1 = *(const ulonglong2*)&bufA[n1 * 48 + c8 + 4];
            ar[0] = f2fma(v0.x, cc, ar[0]);  ai[0] = f2fma(v0.x, ns, ai[0]);
            ar[1] = f2fma(v0.y, cc, ar[1]);  ai[1] = f2fma(v0.y, ns, ai[1]);
            ar[2] = f2fma(v1.x, cc, ar[2]);  ai[2] = f2fma(v1.x, ns, ai[2]);
            ar[3] = f2fma(v1.y, cc, ar[3]);  ai[3] = f2fma(v1.y, ns, ai[3]);
        }
        #pragma unroll
        for (int p = 0; p < 4; p++) {
            float a0, a1, b0, b1;
            upk2(ar[p], a0, a1); upk2(ai[p], b0, b1);
            int n2a = c8 + 2 * p, n2b = n2a + 1;
            float2 ta = g_tw[c * n2a];
            float2 tb = g_tw[c * n2b];
            wre[n2a * 52 + c] = a0 * ta.x + b0 * ta.y;
            wim[n2a * 52 + c] = b0 * ta.x - a0 * ta.y;
            wre[n2b * 52 + c] = a1 * tb.x + b1 * tb.y;
            wim[n2b * 52 + c] = b1 * tb.x - a1 * tb.y;
        }
    }
    __syncthreads();

    // ---- stage 2: F[k2*48+k1] = sum_n2 w[k1][n2] e^{-2pi i k2 n2/48}; scale; modulate
    {
        u64 zr[4], zi[4];
        #pragma unroll
        for (int j = 0; j < 4; j++) { zr[j] = 0ULL; zi[j] = 0ULL; }
        #pragma unroll 4
        for (int n2 = 0; n2 < 48; n2++) {
            float2 w = stcs[n2 * 48 + c];
            u64 cc = pk2(w.x, w.x), ss = pk2(w.y, w.y), ns = pk2(-w.y, -w.y);
            ulonglong2 br0 = *(const ulonglong2*)&wre[n2 * 52 + c8];
            ulonglong2 br1 = *(const ulonglong2*)&wre[n2 * 52 + c8 + 4];
            ulonglong2 bi0 = *(const ulonglong2*)&wim[n2 * 52 + c8];
            ulonglong2 bi1 = *(const ulonglong2*)&wim[n2 * 52 + c8 + 4];
            zr[0] = f2fma(br0.x, cc, zr[0]); zr[0] = f2fma(bi0.x, ss, zr[0]);
            zi[0] = f2fma(bi0.x, cc, zi[0]); zi[0] = f2fma(br0.x, ns, zi[0]);
            zr[1] = f2fma(br0.y, cc, zr[1]); zr[1] = f2fma(bi0.y, ss, zr[1]);
            zi[1] = f2fma(bi0.y, cc, zi[1]); zi[1] = f2fma(br0.y, ns, zi[1]);
            zr[2] = f2fma(br1.x, cc, zr[2]); zr[2] = f2fma(bi1.x, ss, zr[2]);
            zi[2] = f2fma(bi1.x, cc, zi[2]); zi[2] = f2fma(br1.x, ns, zi[2]);
            zr[3] = f2fma(br1.y, cc, zr[3]); zr[3] = f2fma(bi1.y, ss, zr[3]);
            zi[3] = f2fma(bi1.y, cc, zi[3]); zi[3] = f2fma(br1.y, ns, zi[3]);
        }
        const float* fB = g_filt + (long)b * HF + (long)h * FB;
        const float* cB = g_bias + (long)b * HF + (long)h * FB;
        float xr8[8], xi8[8];
        #pragma unroll
        for (int p = 0; p < 4; p++) {
            float r0, r1, i0, i1;
            upk2(zr[p], r0, r1); upk2(zi[p], i0, i1);
            float rr[2] = {r0, r1}, ii[2] = {i0, i1};
            #pragma unroll
            for (int q = 0; q < 2; q++) {
                int j = 2 * p + q;
                int k = c * 48 + c8 + j;
                int f = (k <= 1152) ? k : (2304 - k);
                float gf = fB[f], bb = cB[f];
                float Fr = rr[q] * inv48, Fi = ii[q] * inv48;
                float mr = Fr * gf + bb;
                float mi = Fi * gf;
                float mag = sqrtf(mr * mr + mi * mi);
                float gel = 0.5f * mag * (1.0f + erff(mag * 0.70710678118654752f));
                float fac = gel / (mag + 1e-6f);
                xr8[j] = mr * fac; xi8[j] = mi * fac;
            }
        }
        __syncthreads();  // bufA dead -> reuse as Xr
        float4* pr = (float4*)&bufA[c * 52 + c8];
        pr[0] = make_float4(xr8[0], xr8[1], xr8[2], xr8[3]);
        pr[1] = make_float4(xr8[4], xr8[5], xr8[6], xr8[7]);
        float4* pi = (float4*)&Xim[c * 52 + c8];
        pi[0] = make_float4(xi8[0], xi8[1], xi8[2], xi8[3]);
        pi[1] = make_float4(xi8[4], xi8[5], xi8[6], xi8[7]);
    }
    __syncthreads();

    // ---- stage 3: G[k1][r] = sum_k2 X[k2*48+k1] e^{+2pi i r k2/48}; * e^{+2pi i r k1/N}
    {
        u64 gr[4], gi[4];
        #pragma unroll
        for (int j = 0; j < 4; j++) { gr[j] = 0ULL; gi[j] = 0ULL; }
        #pragma unroll 4
        for (int k2 = 0; k2 < 48; k2++) {
            float2 w = stcs[k2 * 48 + c];
            u64 cc = pk2(w.x, w.x), ss = pk2(w.y, w.y), ns = pk2(-w.y, -w.y);
            ulonglong2 xr0 = *(const ulonglong2*)&bufA[k2 * 52 + c8];
            ulonglong2 xr1 = *(const ulonglong2*)&bufA[k2 * 52 + c8 + 4];
            ulonglong2 xi0 = *(const ulonglong2*)&Xim[k2 * 52 + c8];
            ulonglong2 xi1 = *(const ulonglong2*)&Xim[k2 * 52 + c8 + 4];
            gr[0] = f2fma(xr0.x, cc, gr[0]); gr[0] = f2fma(xi0.x, ns, gr[0]);
            gi[0] = f2fma(xr0.x, ss, gi[0]); gi[0] = f2fma(xi0.x, cc, gi[0]);
            gr[1] = f2fma(xr0.y, cc, gr[1]); gr[1] = f2fma(xi0.y, ns, gr[1]);
            gi[1] = f2fma(xr0.y, ss, gi[1]); gi[1] = f2fma(xi0.y, cc, gi[1]);
            gr[2] = f2fma(xr1.x, cc, gr[2]); gr[2] = f2fma(xi1.x, ns, gr[2]);
            gi[2] = f2fma(xr1.x, ss, gi[2]); gi[2] = f2fma(xi1.x, cc, gi[2]);
            gr[3] = f2fma(xr1.y, cc, gr[3]); gr[3] = f2fma(xi1.y, ns, gr[3]);
            gi[3] = f2fma(xr1.y, ss, gi[3]); gi[3] = f2fma(xi1.y, cc, gi[3]);
        }
        #pragma unroll
        for (int p = 0; p < 4; p++) {
            float a0, a1, b0, b1;
            upk2(gr[p], a0, a1); upk2(gi[p], b0, b1);
            int k1a = c8 + 2 * p, k1b = k1a + 1;
            float2 ta = g_tw[c * k1a];
            float2 tb = g_tw[c * k1b];
            wre[k1a * 52 + c] = a0 * ta.x - b0 * ta.y;
            wim[k1a * 52 + c] = a0 * ta.y + b0 * ta.x;
            wre[k1b * 52 + c] = a1 * tb.x - b1 * tb.y;
            wim[k1b * 52 + c] = a1 * tb.y + b1 * tb.x;
        }
    }
    __syncthreads();

    // ---- stage 4: y[q*48+r] = Re( sum_k1 H[k1][r] e^{+2pi i q k1/48} ) / 48
    {
        u64 y[4];
        #pragma unroll
        for (int j = 0; j < 4; j++) y[j] = 0ULL;
        #pragma unroll 4
        for (int k1 = 0; k1 < 48; k1++) {
            float2 w = stcs[k1 * 48 + c];
            u64 cc = pk2(w.x, w.x), ns = pk2(-w.y, -w.y);
            ulonglong2 hr0 = *(const ulonglong2*)&wre[k1 * 52 + c8];
            ulonglong2 hr1 = *(const ulonglong2*)&wre[k1 * 52 + c8 + 4];
            ulonglong2 hi0 = *(const ulonglong2*)&wim[k1 * 52 + c8];
            ulonglong2 hi1 = *(const ulonglong2*)&wim[k1 * 52 + c8 + 4];
            y[0] = f2fma(hr0.x, cc, y[0]); y[0] = f2fma(hi0.x, ns, y[0]);
            y[1] = f2fma(hr0.y, cc, y[1]); y[1] = f2fma(hi0.y, ns, y[1]);
            y[2] = f2fma(hr1.x, cc, y[2]); y[2] = f2fma(hi1.x, ns, y[2]);
            y[3] = f2fma(hr1.y, cc, y[3]); y[3] = f2fma(hi1.y, ns, y[3]);
        }
        float yv[8];
        #pragma unroll
        for (int p = 0; p < 4; p++) upk2(y[p], yv[2 * p], yv[2 * p + 1]);
        float* dst = g_yt + (long)col * NN + c * 48 + c8;
        *(float4*)dst       = make_float4(yv[0] * inv48, yv[1] * inv48, yv[2] * inv48, yv[3] * inv48);
        *(float4*)(dst + 4) = make_float4(yv[4] * inv48, yv[5] * inv48, yv[6] * inv48, yv[7] * inv48);
    }
}

// ---------------- output ----------------
__global__ void addout_kernel(const float* __restrict__ x, float* __restrict__ out) {
    __shared__ float tile[32][33];
    int b  = blockIdx.z;
    int n0 = blockIdx.x * 32;
    int d0 = blockIdx.y * 32;
    int tx = threadIdx.x, ty = threadIdx.y;
    const float* src = g_yt + ((long)b * DD + d0) * NN + n0;
    #pragma unroll
    for (int i = 0; i < 32; i += 8)
        tile[ty + i][tx] = src[(long)(ty + i) * NN + tx];
    __syncthreads();
    long base = ((long)b * NN + n0) * DD + d0;
    #pragma unroll
    for (int i = 0; i < 32; i += 8)
        out[base + (long)(ty + i) * DD + tx] =
            x[base + (long)(ty + i) * DD + tx] + tile[tx][ty + i];
}

// ---------------- launch ----------------
extern "C" void kernel_launch(void* const* d_in, const int* in_sizes, int n_in,
                              void* d_out, int out_size) {
    const float* x           = (const float*)d_in[0];
    const float* base_filter = (const float*)d_in[1];
    const float* base_bias   = (const float*)d_in[2];
    const float* ln_gamma    = (const float*)d_in[3];
    const float* ln_beta     = (const float*)d_in[4];
    const float* W1          = (const float*)d_in[5];
    const float* b1          = (const float*)d_in[6];
    const float* W2          = (const float*)d_in[7];
    const float* b2          = (const float*)d_in[8];
    float* out = (float*)d_out;

    static bool attr_done = false;
    if (!attr_done) {
        cudaFuncSetAttribute(spectral_kernel,
                             cudaFuncAttributeMaxDynamicSharedMemorySize, SPEC_SMEM);
        attr_done = true;
    }

    init_tw_kernel<<<(NN + 255) / 256, 256>>>();
    ln_t_kernel<<<dim3(NN / 32, BB), 256>>>(x, ln_gamma, ln_beta);
    ctx_kernel<<<(BB * DD) / 8, 256>>>();
    mlp1_kernel<<<BB, 256>>>(W1, b1);
    mlp2_kernel<<<dim3((OUT2 + 255) / 256, BB), 256>>>(W2, b2, base_filter, base_bias);
    spectral_kernel<<<BB * DD, 288, SPEC_SMEM>>>();
    addout_kernel<<<dim3(NN / 32, DD / 32, BB), dim3(32, 8)>>>(x, out);
}

// round 4
// speedup vs baseline: 3.8393x; 1.5019x over previous
#include <cuda_runtime.h>
#include <cuda_bf16.h>

// Problem constants
#define BB   32
#define DD   256
#define NN   2304      // 48*48
#define HEADS 8
#define FB   1153      // NN/2+1
#define HF   (HEADS*FB)        // 9224
#define OUT2 (HEADS*FB*2)      // 18448

// dynamic smem floats: w24(48) + w48(96) + 4 arrays of 2496
#define SPEC_SMEM ((144 + 4*2496) * 4)

// ---------------- scratch ----------------
__device__ float  g_xh  [BB*DD*NN];   // [b][d][n]
__device__ float  g_yt  [BB*DD*NN];   // filtered, [b][d][n]
__device__ float  g_ctx [BB*DD];
__device__ float  g_hmid[BB*DD];
__device__ float  g_filt[BB*HF];
__device__ float  g_bias[BB*HF];
__device__ float2 g_tw  [NN];         // (cos, sin)(2*pi*j/2304)

typedef unsigned long long u64;

// ---------------- packed f32x2 helpers ----------------
__device__ __forceinline__ u64 pk2(float lo, float hi) {
    u64 r; asm("mov.b64 %0, {%1,%2};" : "=l"(r) : "f"(lo), "f"(hi)); return r;
}
__device__ __forceinline__ void upk2(u64 v, float& lo, float& hi) {
    asm("mov.b64 {%0,%1}, %2;" : "=f"(lo), "=f"(hi) : "l"(v));
}
__device__ __forceinline__ u64 f2fma(u64 a, u64 b, u64 c) {
    u64 d; asm("fma.rn.f32x2 %0, %1, %2, %3;" : "=l"(d) : "l"(a), "l"(b), "l"(c)); return d;
}

// ---------------- twiddle init ----------------
__global__ void init_tw_kernel() {
    int j = blockIdx.x * blockDim.x + threadIdx.x;
    if (j < NN) {
        float sv, cv;
        sincospif((float)j * (1.0f / 1152.0f), &sv, &cv);
        g_tw[j] = make_float2(cv, sv);
    }
}

// ---------------- fused LayerNorm + transpose ----------------
__global__ __launch_bounds__(256) void ln_t_kernel(const float* __restrict__ x,
                                                   const float* __restrict__ gamma,
                                                   const float* __restrict__ beta) {
    __shared__ float tile[32 * 257];
    __shared__ float smu[32], srs[32];
    int b  = blockIdx.y;
    int n0 = blockIdx.x * 32;
    int t  = threadIdx.x;

    const float* src = x + ((long)b * NN + n0) * DD;
    #pragma unroll
    for (int l = t; l < 32 * DD; l += 256) {
        int r = l >> 8, d = l & 255;
        tile[r * 257 + d] = src[l];
    }
    __syncthreads();

    int w = t >> 5, lane = t & 31;
    #pragma unroll
    for (int r = w; r < 32; r += 8) {
        float s = 0.f, s2 = 0.f;
        #pragma unroll
        for (int j = 0; j < 8; j++) {
            float v = tile[r * 257 + lane + j * 32];
            s += v; s2 += v * v;
        }
        #pragma unroll
        for (int o = 16; o; o >>= 1) {
            s  += __shfl_xor_sync(0xffffffffu, s, o);
            s2 += __shfl_xor_sync(0xffffffffu, s2, o);
        }
        if (lane == 0) {
            float mu = s * (1.0f / 256.0f);
            smu[r] = mu;
            srs[r] = rsqrtf(s2 * (1.0f / 256.0f) - mu * mu + 1e-5f);
        }
    }
    __syncthreads();

    #pragma unroll
    for (int l = t; l < 32 * DD; l += 256) {
        int d = l >> 5, i = l & 31;
        float v = (tile[i * 257 + d] - smu[i]) * srs[i] * gamma[d] + beta[d];
        g_xh[((long)b * DD + d) * NN + n0 + i] = v;
    }
}

// ---------------- context ----------------
__global__ void ctx_kernel() {
    int idx  = blockIdx.x * 8 + (threadIdx.x >> 5);
    int lane = threadIdx.x & 31;
    const float* p = g_xh + (long)idx * NN;
    float s = 0.f;
    for (int n = lane; n < NN; n += 32) s += p[n];
    #pragma unroll
    for (int o = 16; o; o >>= 1) s += __shfl_xor_sync(0xffffffffu, s, o);
    if (lane == 0) g_ctx[idx] = s * (1.0f / NN);
}

// ---------------- MLP layer 1 (4-way split-K) ----------------
__global__ __launch_bounds__(256) void mlp1_kernel(const float* __restrict__ W1,
                                                   const float* __restrict__ b1) {
    __shared__ float sc[DD];
    __shared__ float part[4][64];
    int b = blockIdx.x, o0 = blockIdx.y * 64;
    int t = threadIdx.x;
    sc[t] = g_ctx[b * DD + t];
    __syncthreads();
    int ol = t & 63, kp = t >> 6;
    int o = o0 + ol;
    float acc = 0.f;
    #pragma unroll 8
    for (int d = kp * 64; d < kp * 64 + 64; d++) acc += sc[d] * W1[d * DD + o];
    part[kp][ol] = acc;
    __syncthreads();
    if (t < 64) {
        float a = part[0][t] + part[1][t] + part[2][t] + part[3][t] + b1[o0 + t];
        g_hmid[b * DD + o0 + t] = 0.5f * a * (1.0f + erff(a * 0.70710678118654752f));
    }
}

// ---------------- MLP layer 2 ----------------
__global__ void mlp2_kernel(const float* __restrict__ W2, const float* __restrict__ b2,
                            const float* __restrict__ base_filter,
                            const float* __restrict__ base_bias) {
    __shared__ float sh[DD];
    int b = blockIdx.y, t = threadIdx.x;
    sh[t] = g_hmid[b * DD + t];
    __syncthreads();
    int o = blockIdx.x * 256 + t;
    if (o >= OUT2) return;
    float acc = b2[o];
    #pragma unroll 8
    for (int j = 0; j < DD; j++) acc += sh[j] * W2[(long)j * OUT2 + o];
    int idx2 = o >> 1;
    if ((o & 1) == 0)
        g_filt[(long)b * HF + idx2] = base_filter[idx2] * (1.0f + acc);
    else
        g_bias[(long)b * HF + idx2] = base_bias[idx2] + acc;
}

// ---------------- spectral kernel (radix-2 DIT, packed f32x2) ----------------
// 288 threads: e = t%24 (k-lanes e, e+24), grp = t/24 -> 4 columns.
__global__ __launch_bounds__(288) void spectral_kernel() {
    extern __shared__ float sm[];
    float2* w24tab = (float2*)sm;          // 24 entries
    float2* w48tab = (float2*)(sm + 48);   // 48 entries
    float*  bufA = sm + 144;               // 2496: sx / Xr
    float*  Xim  = sm + 2640;              // 2496
    float*  wre  = sm + 5136;              // 2496
    float*  wim  = sm + 7632;              // 2496

    int col = blockIdx.x;
    int b = col >> 8, d = col & 255, h = d >> 5;
    int t = threadIdx.x;
    int e    = t % 24;
    int col4 = (t / 24) * 4;
    const float inv48 = 1.0f / 48.0f;

    if (t < 24) w24tab[t] = g_tw[96 * t];
    else if (t < 72) w48tab[t - 24] = g_tw[48 * (t - 24)];
    const float* src = g_xh + (long)col * NN;
    for (int i = t; i < NN; i += 288) bufA[i] = src[i];
    __syncthreads();

    // ---- stage 1 (fwd, real input): rows n1 of bufA (stride 48) ----
    {
        u64 Er[2] = {0,0}, Ei[2] = {0,0}, Orr[2] = {0,0}, Oii[2] = {0,0};
        int idx = 0;
        #pragma unroll 4
        for (int m = 0; m < 24; m++) {
            float2 w = w24tab[idx]; idx += e; if (idx >= 24) idx -= 24;
            u64 cc = pk2(w.x, w.x), ns = pk2(-w.y, -w.y);
            ulonglong2 ve = *(const ulonglong2*)&bufA[(2*m)   * 48 + col4];
            ulonglong2 vo = *(const ulonglong2*)&bufA[(2*m+1) * 48 + col4];
            Er[0] = f2fma(ve.x, cc, Er[0]);  Ei[0] = f2fma(ve.x, ns, Ei[0]);
            Er[1] = f2fma(ve.y, cc, Er[1]);  Ei[1] = f2fma(ve.y, ns, Ei[1]);
            Orr[0]= f2fma(vo.x, cc, Orr[0]); Oii[0]= f2fma(vo.x, ns, Oii[0]);
            Orr[1]= f2fma(vo.y, cc, Orr[1]); Oii[1]= f2fma(vo.y, ns, Oii[1]);
        }
        float er[4], ei[4], orr[4], oii[4];
        upk2(Er[0], er[0], er[1]);  upk2(Er[1], er[2], er[3]);
        upk2(Ei[0], ei[0], ei[1]);  upk2(Ei[1], ei[2], ei[3]);
        upk2(Orr[0], orr[0], orr[1]); upk2(Orr[1], orr[2], orr[3]);
        upk2(Oii[0], oii[0], oii[1]); upk2(Oii[1], oii[2], oii[3]);
        float2 t48 = w48tab[e];   // w48^e = (c, -s) forward
        #pragma unroll
        for (int j = 0; j < 4; j++) {
            float tr = orr[j] * t48.x + oii[j] * t48.y;
            float ti = oii[j] * t48.x - orr[j] * t48.y;
            float xre = er[j] + tr, xie = ei[j] + ti;   // k1 = e
            float xro = er[j] - tr, xio = ei[j] - ti;   // k1 = e+24
            int n2 = col4 + j;
            float2 ta = g_tw[e * n2];
            wre[n2 * 52 + e]      = xre * ta.x + xie * ta.y;
            wim[n2 * 52 + e]      = xie * ta.x - xre * ta.y;
            float2 tb = g_tw[(e + 24) * n2];
            wre[n2 * 52 + e + 24] = xro * tb.x + xio * tb.y;
            wim[n2 * 52 + e + 24] = xio * tb.x - xro * tb.y;
        }
    }
    __syncthreads();

    // ---- stage 2 (fwd, complex): rows n2 of wre/wim (stride 52), cols k1 ----
    {
        u64 Er[2]={0,0}, Ei[2]={0,0}, Orr[2]={0,0}, Oii[2]={0,0};
        int idx = 0;
        #pragma unroll 4
        for (int m = 0; m < 24; m++) {
            float2 w = w24tab[idx]; idx += e; if (idx >= 24) idx -= 24;
            u64 cc = pk2(w.x, w.x), ss = pk2(w.y, w.y), ns = pk2(-w.y, -w.y);
            ulonglong2 are = *(const ulonglong2*)&wre[(2*m)   * 52 + col4];
            ulonglong2 aie = *(const ulonglong2*)&wim[(2*m)   * 52 + col4];
            ulonglong2 aro = *(const ulonglong2*)&wre[(2*m+1) * 52 + col4];
            ulonglong2 aio = *(const ulonglong2*)&wim[(2*m+1) * 52 + col4];
            Er[0] = f2fma(are.x, cc, Er[0]); Er[0] = f2fma(aie.x, ss, Er[0]);
            Ei[0] = f2fma(aie.x, cc, Ei[0]); Ei[0] = f2fma(are.x, ns, Ei[0]);
            Er[1] = f2fma(are.y, cc, Er[1]); Er[1] = f2fma(aie.y, ss, Er[1]);
            Ei[1] = f2fma(aie.y, cc, Ei[1]); Ei[1] = f2fma(are.y, ns, Ei[1]);
            Orr[0]= f2fma(aro.x, cc, Orr[0]); Orr[0]= f2fma(aio.x, ss, Orr[0]);
            Oii[0]= f2fma(aio.x, cc, Oii[0]); Oii[0]= f2fma(aro.x, ns, Oii[0]);
            Orr[1]= f2fma(aro.y, cc, Orr[1]); Orr[1]= f2fma(aio.y, ss, Orr[1]);
            Oii[1]= f2fma(aio.y, cc, Oii[1]); Oii[1]= f2fma(aro.y, ns, Oii[1]);
        }
        float er[4], ei[4], orr[4], oii[4];
        upk2(Er[0], er[0], er[1]);  upk2(Er[1], er[2], er[3]);
        upk2(Ei[0], ei[0], ei[1]);  upk2(Ei[1], ei[2], ei[3]);
        upk2(Orr[0], orr[0], orr[1]); upk2(Orr[1], orr[2], orr[3]);
        upk2(Oii[0], oii[0], oii[1]); upk2(Oii[1], oii[2], oii[3]);
        float2 t48 = w48tab[e];
        const float* fB = g_filt + (long)b * HF + (long)h * FB;
        const float* cB = g_bias + (long)b * HF + (long)h * FB;
        float xeR[4], xeI[4], xoR[4], xoI[4];
        #pragma unroll
        for (int j = 0; j < 4; j++) {
            float tr = orr[j] * t48.x + oii[j] * t48.y;
            float ti = oii[j] * t48.x - orr[j] * t48.y;
            float Fr0 = (er[j] + tr) * inv48, Fi0 = (ei[j] + ti) * inv48;  // k2 = e
            float Fr1 = (er[j] - tr) * inv48, Fi1 = (ei[j] - ti) * inv48;  // k2 = e+24
            int k0 = e * 48 + col4 + j;
            int f0 = (k0 <= 1152) ? k0 : (2304 - k0);
            float gf = fB[f0], bb = cB[f0];
            float mr = Fr0 * gf + bb, mi = Fi0 * gf;
            float mag = sqrtf(mr * mr + mi * mi);
            float fac = 0.5f * mag * (1.0f + erff(mag * 0.70710678118654752f)) / (mag + 1e-6f);
            xeR[j] = mr * fac; xeI[j] = mi * fac;
            int k1v = (e + 24) * 48 + col4 + j;
            int f1 = (k1v <= 1152) ? k1v : (2304 - k1v);
            gf = fB[f1]; bb = cB[f1];
            mr = Fr1 * gf + bb; mi = Fi1 * gf;
            mag = sqrtf(mr * mr + mi * mi);
            fac = 0.5f * mag * (1.0f + erff(mag * 0.70710678118654752f)) / (mag + 1e-6f);
            xoR[j] = mr * fac; xoI[j] = mi * fac;
        }
        *(float4*)&bufA[e * 52 + col4]        = make_float4(xeR[0], xeR[1], xeR[2], xeR[3]);
        *(float4*)&Xim [e * 52 + col4]        = make_float4(xeI[0], xeI[1], xeI[2], xeI[3]);
        *(float4*)&bufA[(e + 24) * 52 + col4] = make_float4(xoR[0], xoR[1], xoR[2], xoR[3]);
        *(float4*)&Xim [(e + 24) * 52 + col4] = make_float4(xoI[0], xoI[1], xoI[2], xoI[3]);
    }
    __syncthreads();

    // ---- stage 3 (inv, complex): rows k2 of bufA/Xim (stride 52), cols k1; outputs r ----
    {
        u64 Er[2]={0,0}, Ei[2]={0,0}, Orr[2]={0,0}, Oii[2]={0,0};
        int idx = 0;
        #pragma unroll 4
        for (int m = 0; m < 24; m++) {
            float2 w = w24tab[idx]; idx += e; if (idx >= 24) idx -= 24;
            u64 cc = pk2(w.x, w.x), ss = pk2(w.y, w.y), ns = pk2(-w.y, -w.y);
            ulonglong2 xre = *(const ulonglong2*)&bufA[(2*m)   * 52 + col4];
            ulonglong2 xie = *(const ulonglong2*)&Xim [(2*m)   * 52 + col4];
            ulonglong2 xro = *(const ulonglong2*)&bufA[(2*m+1) * 52 + col4];
            ulonglong2 xio = *(const ulonglong2*)&Xim [(2*m+1) * 52 + col4];
            Er[0] = f2fma(xre.x, cc, Er[0]); Er[0] = f2fma(xie.x, ns, Er[0]);
            Ei[0] = f2fma(xie.x, cc, Ei[0]); Ei[0] = f2fma(xre.x, ss, Ei[0]);
            Er[1] = f2fma(xre.y, cc, Er[1]); Er[1] = f2fma(xie.y, ns, Er[1]);
            Ei[1] = f2fma(xie.y, cc, Ei[1]); Ei[1] = f2fma(xre.y, ss, Ei[1]);
            Orr[0]= f2fma(xro.x, cc, Orr[0]); Orr[0]= f2fma(xio.x, ns, Orr[0]);
            Oii[0]= f2fma(xio.x, cc, Oii[0]); Oii[0]= f2fma(xro.x, ss, Oii[0]);
            Orr[1]= f2fma(xro.y, cc, Orr[1]); Orr[1]= f2fma(xio.y, ns, Orr[1]);
            Oii[1]= f2fma(xio.y, cc, Oii[1]); Oii[1]= f2fma(xro.y, ss, Oii[1]);
        }
        float er[4], ei[4], orr[4], oii[4];
        upk2(Er[0], er[0], er[1]);  upk2(Er[1], er[2], er[3]);
        upk2(Ei[0], ei[0], ei[1]);  upk2(Ei[1], ei[2], ei[3]);
        upk2(Orr[0], orr[0], orr[1]); upk2(Orr[1], orr[2], orr[3]);
        upk2(Oii[0], oii[0], oii[1]); upk2(Oii[1], oii[2], oii[3]);
        float2 t48 = w48tab[e];   // inverse: t = (c, +s)
        #pragma unroll
        for (int j = 0; j < 4; j++) {
            float tr = orr[j] * t48.x - oii[j] * t48.y;
            float ti = orr[j] * t48.y + oii[j] * t48.x;
            float gre = er[j] + tr, gie = ei[j] + ti;   // r = e
            float gro = er[j] - tr, gio = ei[j] - ti;   // r = e+24
            int k1 = col4 + j;
            float2 ta = g_tw[e * k1];
            wre[k1 * 52 + e]      = gre * ta.x - gie * ta.y;
            wim[k1 * 52 + e]      = gre * ta.y + gie * ta.x;
            float2 tb = g_tw[(e + 24) * k1];
            wre[k1 * 52 + e + 24] = gro * tb.x - gio * tb.y;
            wim[k1 * 52 + e + 24] = gro * tb.y + gio * tb.x;
        }
    }
    __syncthreads();

    // ---- stage 4 (inv, real output): rows k1 of wre/wim (stride 52), cols r; outputs q ----
    {
        u64 Er[2]={0,0}, Orr[2]={0,0}, Oii[2]={0,0};
        int idx = 0;
        #pragma unroll 4
        for (int m = 0; m < 24; m++) {
            float2 w = w24tab[idx]; idx += e; if (idx >= 24) idx -= 24;
            u64 cc = pk2(w.x, w.x), ss = pk2(w.y, w.y), ns = pk2(-w.y, -w.y);
            ulonglong2 hre = *(const ulonglong2*)&wre[(2*m)   * 52 + col4];
            ulonglong2 hie = *(const ulonglong2*)&wim[(2*m)   * 52 + col4];
            ulonglong2 hro = *(const ulonglong2*)&wre[(2*m+1) * 52 + col4];
            ulonglong2 hio = *(const ulonglong2*)&wim[(2*m+1) * 52 + col4];
            Er[0] = f2fma(hre.x, cc, Er[0]); Er[0] = f2fma(hie.x, ns, Er[0]);
            Er[1] = f2fma(hre.y, cc, Er[1]); Er[1] = f2fma(hie.y, ns, Er[1]);
            Orr[0]= f2fma(hro.x, cc, Orr[0]); Orr[0]= f2fma(hio.x, ns, Orr[0]);
            Oii[0]= f2fma(hio.x, cc, Oii[0]); Oii[0]= f2fma(hro.x, ss, Oii[0]);
            Orr[1]= f2fma(hro.y, cc, Orr[1]); Orr[1]= f2fma(hio.y, ns, Orr[1]);
            Oii[1]= f2fma(hio.y, cc, Oii[1]); Oii[1]= f2fma(hro.y, ss, Oii[1]);
        }
        float er[4], orr[4], oii[4];
        upk2(Er[0], er[0], er[1]);  upk2(Er[1], er[2], er[3]);
        upk2(Orr[0], orr[0], orr[1]); upk2(Orr[1], orr[2], orr[3]);
        upk2(Oii[0], oii[0], oii[1]); upk2(Oii[1], oii[2], oii[3]);
        float2 t48 = w48tab[e];
        float ye[4], yo[4];
        #pragma unroll
        for (int j = 0; j < 4; j++) {
            float tr = orr[j] * t48.x - oii[j] * t48.y;   // Re(t*O), t=(c,+s)
            ye[j] = (er[j] + tr) * inv48;
            yo[j] = (er[j] - tr) * inv48;
        }
        float* dst = g_yt + (long)col * NN;
        *(float4*)&dst[e * 48 + col4]        = make_float4(ye[0], ye[1], ye[2], ye[3]);
        *(float4*)&dst[(e + 24) * 48 + col4] = make_float4(yo[0], yo[1], yo[2], yo[3]);
    }
}

// ---------------- output ----------------
__global__ void addout_kernel(const float* __restrict__ x, float* __restrict__ out) {
    __shared__ float tile[32][33];
    int b  = blockIdx.z;
    int n0 = blockIdx.x * 32;
    int d0 = blockIdx.y * 32;
    int tx = threadIdx.x, ty = threadIdx.y;
    const float* src = g_yt + ((long)b * DD + d0) * NN + n0;
    #pragma unroll
    for (int i = 0; i < 32; i += 8)
        tile[ty + i][tx] = src[(long)(ty + i) * NN + tx];
    __syncthreads();
    long base = ((long)b * NN + n0) * DD + d0;
    #pragma unroll
    for (int i = 0; i < 32; i += 8)
        out[base + (long)(ty + i) * DD + tx] =
            x[base + (long)(ty + i) * DD + tx] + tile[tx][ty + i];
}

// ---------------- launch ----------------
extern "C" void kernel_launch(void* const* d_in, const int* in_sizes, int n_in,
                              void* d_out, int out_size) {
    const float* x           = (const float*)d_in[0];
    const float* base_filter = (const float*)d_in[1];
    const float* base_bias   = (const float*)d_in[2];
    const float* ln_gamma    = (const float*)d_in[3];
    const float* ln_beta     = (const float*)d_in[4];
    const float* W1          = (const float*)d_in[5];
    const float* b1          = (const float*)d_in[6];
    const float* W2          = (const float*)d_in[7];
    const float* b2          = (const float*)d_in[8];
    float* out = (float*)d_out;

    static bool attr_done = false;
    if (!attr_done) {
        cudaFuncSetAttribute(spectral_kernel,
                             cudaFuncAttributeMaxDynamicSharedMemorySize, SPEC_SMEM);
        attr_done = true;
    }

    init_tw_kernel<<<(NN + 255) / 256, 256>>>();
    ln_t_kernel<<<dim3(NN / 32, BB), 256>>>(x, ln_gamma, ln_beta);
    ctx_kernel<<<(BB * DD) / 8, 256>>>();
    mlp1_kernel<<<dim3(BB, 4), 256>>>(W1, b1);
    mlp2_kernel<<<dim3((OUT2 + 255) / 256, BB), 256>>>(W2, b2, base_filter, base_bias);
    spectral_kernel<<<BB * DD, 288, SPEC_SMEM>>>();
    addout_kernel<<<dim3(NN / 32, DD / 32, BB), dim3(32, 8)>>>(x, out);
}

// round 5
// speedup vs baseline: 4.9575x; 1.2913x over previous
#include <cuda_runtime.h>
#include <cuda_bf16.h>

// Problem constants
#define BB   32
#define DD   256
#define NN   2304      // 48*48
#define HEADS 8
#define FB   1153      // NN/2+1
#define HF   (HEADS*FB)        // 9224
#define OUT2 (HEADS*FB*2)      // 18448

// ---------------- scratch ----------------
__device__ float  g_xh   [BB*DD*NN];   // [b][d][n]
__device__ float  g_yt   [BB*DD*NN];   // filtered, [b][d][n]
__device__ float  g_ctx  [BB*DD];      // raw sums (atomic), scaled in mlp1
__device__ float  g_hmidT[DD*BB];      // transposed: [o][b]
__device__ float  g_filt [BB*HF];
__device__ float  g_bias [BB*HF];
__device__ float2 g_tw   [NN];         // (cos, sin)(2*pi*j/2304)

typedef unsigned long long u64;

// ---------------- packed f32x2 helpers ----------------
__device__ __forceinline__ u64 pk2(float lo, float hi) {
    u64 r; asm("mov.b64 %0, {%1,%2};" : "=l"(r) : "f"(lo), "f"(hi)); return r;
}
__device__ __forceinline__ void upk2(u64 v, float& lo, float& hi) {
    asm("mov.b64 {%0,%1}, %2;" : "=f"(lo), "=f"(hi) : "l"(v));
}
__device__ __forceinline__ u64 f2fma(u64 a, u64 b, u64 c) {
    u64 d; asm("fma.rn.f32x2 %0, %1, %2, %3;" : "=l"(d) : "l"(a), "l"(b), "l"(c)); return d;
}
__device__ __forceinline__ u64 add2(u64 a, u64 b) {
    u64 d; asm("add.rn.f32x2 %0, %1, %2;" : "=l"(d) : "l"(a), "l"(b)); return d;
}
__device__ __forceinline__ u64 mul2(u64 a, u64 b) {
    u64 d; asm("mul.rn.f32x2 %0, %1, %2;" : "=l"(d) : "l"(a), "l"(b)); return d;
}

// ---------------- init: twiddles + zero ctx ----------------
__global__ void init_kernel() {
    int j = blockIdx.x * blockDim.x + threadIdx.x;   // 8192 threads
    if (j < NN) {
        float sv, cv;
        sincospif((float)j * (1.0f / 1152.0f), &sv, &cv);
        g_tw[j] = make_float2(cv, sv);
    }
    g_ctx[j] = 0.f;
}

// ---------------- fused LayerNorm + transpose + ctx partials ----------------
__global__ __launch_bounds__(256) void ln_t_kernel(const float* __restrict__ x,
                                                   const float* __restrict__ gamma,
                                                   const float* __restrict__ beta) {
    __shared__ float tile[32 * 257];
    __shared__ float smu[32], srs[32];
    int b  = blockIdx.y;
    int n0 = blockIdx.x * 32;
    int t  = threadIdx.x;

    const float* src = x + ((long)b * NN + n0) * DD;
    #pragma unroll
    for (int l = t; l < 32 * DD; l += 256) {
        int r = l >> 8, d = l & 255;
        tile[r * 257 + d] = src[l];
    }
    __syncthreads();

    int w = t >> 5, lane = t & 31;
    #pragma unroll
    for (int r = w; r < 32; r += 8) {
        float s = 0.f, s2 = 0.f;
        #pragma unroll
        for (int j = 0; j < 8; j++) {
            float v = tile[r * 257 + lane + j * 32];
            s += v; s2 += v * v;
        }
        #pragma unroll
        for (int o = 16; o; o >>= 1) {
            s  += __shfl_xor_sync(0xffffffffu, s, o);
            s2 += __shfl_xor_sync(0xffffffffu, s2, o);
        }
        if (lane == 0) {
            float mu = s * (1.0f / 256.0f);
            smu[r] = mu;
            srs[r] = rsqrtf(s2 * (1.0f / 256.0f) - mu * mu + 1e-5f);
        }
    }
    __syncthreads();

    #pragma unroll
    for (int l = t; l < 32 * DD; l += 256) {
        int d = l >> 5, i = l & 31;   // d is warp-uniform
        float v = (tile[i * 257 + d] - smu[i]) * srs[i] * gamma[d] + beta[d];
        g_xh[((long)b * DD + d) * NN + n0 + i] = v;
        float sv = v;
        #pragma unroll
        for (int o = 16; o; o >>= 1) sv += __shfl_xor_sync(0xffffffffu, sv, o);
        if (lane == 0) atomicAdd(&g_ctx[b * DD + d], sv);
    }
}

// ---------------- MLP layer 1 (4-way split-K) -> hmidT ----------------
__global__ __launch_bounds__(256) void mlp1_kernel(const float* __restrict__ W1,
                                                   const float* __restrict__ b1) {
    __shared__ float sc[DD];
    __shared__ float part[4][64];
    int b = blockIdx.x, o0 = blockIdx.y * 64;
    int t = threadIdx.x;
    sc[t] = g_ctx[b * DD + t] * (1.0f / NN);
    __syncthreads();
    int ol = t & 63, kp = t >> 6;
    int o = o0 + ol;
    float acc = 0.f;
    #pragma unroll 8
    for (int d = kp * 64; d < kp * 64 + 64; d++) acc += sc[d] * W1[d * DD + o];
    part[kp][ol] = acc;
    __syncthreads();
    if (t < 64) {
        float a = part[0][t] + part[1][t] + part[2][t] + part[3][t] + b1[o0 + t];
        g_hmidT[(o0 + t) * BB + b] = 0.5f * a * (1.0f + erff(a * 0.70710678118654752f));
    }
}

// ---------------- MLP layer 2 (batched over b, W2 read once) ----------------
__global__ __launch_bounds__(256) void mlp2_kernel(const float* __restrict__ W2,
                                                   const float* __restrict__ b2,
                                                   const float* __restrict__ base_filter,
                                                   const float* __restrict__ base_bias) {
    __shared__ float sh[DD * BB];   // hmidT copy: [j][b]
    int t = threadIdx.x;
    #pragma unroll
    for (int i = t; i < DD * BB; i += 256) sh[i] = g_hmidT[i];
    __syncthreads();

    int ol = t & 63, bg = t >> 6;
    int o = blockIdx.x * 64 + ol;
    if (o >= OUT2) return;
    int b0 = bg * 8;

    u64 acc0 = 0, acc1 = 0, acc2 = 0, acc3 = 0;
    #pragma unroll 4
    for (int j = 0; j < DD; j++) {
        float wv = W2[(long)j * OUT2 + o];
        u64 wp = pk2(wv, wv);
        const u64* hp = (const u64*)&sh[j * BB + b0];
        acc0 = f2fma(hp[0], wp, acc0);
        acc1 = f2fma(hp[1], wp, acc1);
        acc2 = f2fma(hp[2], wp, acc2);
        acc3 = f2fma(hp[3], wp, acc3);
    }
    float a[8];
    upk2(acc0, a[0], a[1]); upk2(acc1, a[2], a[3]);
    upk2(acc2, a[4], a[5]); upk2(acc3, a[6], a[7]);
    float bias2 = b2[o];
    int idx2 = o >> 1;
    if ((o & 1) == 0) {
        float base = base_filter[idx2];
        #pragma unroll
        for (int r = 0; r < 8; r++)
            g_filt[(long)(b0 + r) * HF + idx2] = base * (1.0f + a[r] + bias2);
    } else {
        float base = base_bias[idx2];
        #pragma unroll
        for (int r = 0; r < 8; r++)
            g_bias[(long)(b0 + r) * HF + idx2] = base + a[r] + bias2;
    }
}

// ---------------- spectral kernel: radix-4 (48 = 4x12), packed f32x2 ----------------
// 288 threads: e = t%12 (outputs e, e+12, e+24, e+36), g = t/12 -> cols c2 = 2g, 2g+1
__global__ __launch_bounds__(288) void spectral_kernel() {
    __shared__ float sm[120 + 4 * 2496];
    float2* w12 = (float2*)sm;             // 12 entries @ [0,24)
    float2* w48 = (float2*)(sm + 24);      // 48 entries @ [24,120)
    float*  bufA = sm + 120;               // 2496: x (stride 48), later Xr (stride 52)
    float*  Xim  = bufA + 2496;
    float*  wre  = Xim + 2496;
    float*  wim  = wre + 2496;

    int col = blockIdx.x;
    int b = col >> 8, d = col & 255, h = d >> 5;
    int t = threadIdx.x;
    int e  = t % 12;
    int c2 = (t / 12) * 2;
    const float inv48 = 1.0f / 48.0f;
    const u64 NEG1 = pk2(-1.0f, -1.0f);

    if (t < 12) w12[t] = g_tw[192 * t];
    else if (t < 60) w48[t - 12] = g_tw[48 * (t - 12)];
    const float* src = g_xh + (long)col * NN;
    for (int i = t; i < NN; i += 288) bufA[i] = src[i];
    __syncthreads();

    float2 we1 = {0,0}, we2 = {0,0}, we3 = {0,0};
    // (filled after tables ready)
    we1 = w48[e]; we2 = w48[2 * e]; we3 = w48[3 * e];

    // ======== stage 1: forward over n1 (real input), rows stride 48 ========
    {
        u64 S0r=0,S0i=0,S1r=0,S1i=0,S2r=0,S2i=0,S3r=0,S3i=0;
        int idx = 0;
        #pragma unroll 4
        for (int m = 0; m < 12; m++) {
            float2 w = w12[idx]; idx += e; if (idx >= 12) idx -= 12;
            u64 cc = pk2(w.x, w.x), ns = pk2(-w.y, -w.y);
            u64 v0 = *(const u64*)&bufA[(4*m+0)*48 + c2];
            u64 v1 = *(const u64*)&bufA[(4*m+1)*48 + c2];
            u64 v2 = *(const u64*)&bufA[(4*m+2)*48 + c2];
            u64 v3 = *(const u64*)&bufA[(4*m+3)*48 + c2];
            S0r = f2fma(v0, cc, S0r); S0i = f2fma(v0, ns, S0i);
            S1r = f2fma(v1, cc, S1r); S1i = f2fma(v1, ns, S1i);
            S2r = f2fma(v2, cc, S2r); S2i = f2fma(v2, ns, S2i);
            S3r = f2fma(v3, cc, S3r); S3i = f2fma(v3, ns, S3i);
        }
        // forward T = (c,-s)*S:  Tr = Sr c + Si s ; Ti = Si c - Sr s
        u64 c1=pk2(we1.x,we1.x), s1=pk2(we1.y,we1.y), n1=pk2(-we1.y,-we1.y);
        u64 c2p=pk2(we2.x,we2.x), s2p=pk2(we2.y,we2.y), n2p=pk2(-we2.y,-we2.y);
        u64 c3=pk2(we3.x,we3.x), s3=pk2(we3.y,we3.y), n3=pk2(-we3.y,-we3.y);
        u64 T1r = f2fma(S1i, s1, mul2(S1r, c1)),  T1i = f2fma(S1r, n1, mul2(S1i, c1));
        u64 T2r = f2fma(S2i, s2p, mul2(S2r, c2p)), T2i = f2fma(S2r, n2p, mul2(S2i, c2p));
        u64 T3r = f2fma(S3i, s3, mul2(S3r, c3)),  T3i = f2fma(S3r, n3, mul2(S3i, c3));
        u64 ar = add2(S0r, T2r), ai = add2(S0i, T2i);
        u64 br = f2fma(T2r, NEG1, S0r), bi = f2fma(T2i, NEG1, S0i);
        u64 cr = add2(T1r, T3r), ci = add2(T1i, T3i);
        u64 dr = f2fma(T3r, NEG1, T1r), di = f2fma(T3i, NEG1, T1i);
        u64 Xr[4], Xi4[4];
        Xr[0] = add2(ar, cr);          Xi4[0] = add2(ai, ci);
        Xr[1] = add2(br, di);          Xi4[1] = f2fma(dr, NEG1, bi);   // b - i d
        Xr[2] = f2fma(cr, NEG1, ar);   Xi4[2] = f2fma(ci, NEG1, ai);
        Xr[3] = f2fma(di, NEG1, br);   Xi4[3] = add2(bi, dr);          // b + i d
        #pragma unroll
        for (int p = 0; p < 4; p++) {
            float r0, r1, i0, i1;
            upk2(Xr[p], r0, r1); upk2(Xi4[p], i0, i1);
            int k = e + 12 * p;
            float2 ta = g_tw[k * c2];
            wre[c2 * 52 + k]       = r0 * ta.x + i0 * ta.y;
            wim[c2 * 52 + k]       = i0 * ta.x - r0 * ta.y;
            float2 tb = g_tw[k * (c2 + 1)];
            wre[(c2 + 1) * 52 + k] = r1 * tb.x + i1 * tb.y;
            wim[(c2 + 1) * 52 + k] = i1 * tb.x - r1 * tb.y;
        }
    }
    __syncthreads();

    // ======== stage 2: forward over n2 (complex), rows stride 52; modulate ========
    {
        u64 S0r=0,S0i=0,S1r=0,S1i=0,S2r=0,S2i=0,S3r=0,S3i=0;
        int idx = 0;
        #pragma unroll 4
        for (int m = 0; m < 12; m++) {
            float2 w = w12[idx]; idx += e; if (idx >= 12) idx -= 12;
            u64 cc = pk2(w.x, w.x), ss = pk2(w.y, w.y), ns = pk2(-w.y, -w.y);
            u64 vr0 = *(const u64*)&wre[(4*m+0)*52 + c2], vi0 = *(const u64*)&wim[(4*m+0)*52 + c2];
            u64 vr1 = *(const u64*)&wre[(4*m+1)*52 + c2], vi1 = *(const u64*)&wim[(4*m+1)*52 + c2];
            u64 vr2 = *(const u64*)&wre[(4*m+2)*52 + c2], vi2 = *(const u64*)&wim[(4*m+2)*52 + c2];
            u64 vr3 = *(const u64*)&wre[(4*m+3)*52 + c2], vi3 = *(const u64*)&wim[(4*m+3)*52 + c2];
            S0r = f2fma(vr0, cc, S0r); S0r = f2fma(vi0, ss, S0r);
            S0i = f2fma(vi0, cc, S0i); S0i = f2fma(vr0, ns, S0i);
            S1r = f2fma(vr1, cc, S1r); S1r = f2fma(vi1, ss, S1r);
            S1i = f2fma(vi1, cc, S1i); S1i = f2fma(vr1, ns, S1i);
            S2r = f2fma(vr2, cc, S2r); S2r = f2fma(vi2, ss, S2r);
            S2i = f2fma(vi2, cc, S2i); S2i = f2fma(vr2, ns, S2i);
            S3r = f2fma(vr3, cc, S3r); S3r = f2fma(vi3, ss, S3r);
            S3i = f2fma(vi3, cc, S3i); S3i = f2fma(vr3, ns, S3i);
        }
        u64 c1=pk2(we1.x,we1.x), s1=pk2(we1.y,we1.y), n1=pk2(-we1.y,-we1.y);
        u64 c2p=pk2(we2.x,we2.x), s2p=pk2(we2.y,we2.y), n2p=pk2(-we2.y,-we2.y);
        u64 c3=pk2(we3.x,we3.x), s3=pk2(we3.y,we3.y), n3=pk2(-we3.y,-we3.y);
        u64 T1r = f2fma(S1i, s1, mul2(S1r, c1)),  T1i = f2fma(S1r, n1, mul2(S1i, c1));
        u64 T2r = f2fma(S2i, s2p, mul2(S2r, c2p)), T2i = f2fma(S2r, n2p, mul2(S2i, c2p));
        u64 T3r = f2fma(S3i, s3, mul2(S3r, c3)),  T3i = f2fma(S3r, n3, mul2(S3i, c3));
        u64 ar = add2(S0r, T2r), ai = add2(S0i, T2i);
        u64 br = f2fma(T2r, NEG1, S0r), bi = f2fma(T2i, NEG1, S0i);
        u64 cr = add2(T1r, T3r), ci = add2(T1i, T3i);
        u64 dr = f2fma(T3r, NEG1, T1r), di = f2fma(T3i, NEG1, T1i);
        u64 Xr[4], Xi4[4];
        Xr[0] = add2(ar, cr);          Xi4[0] = add2(ai, ci);
        Xr[1] = add2(br, di);          Xi4[1] = f2fma(dr, NEG1, bi);
        Xr[2] = f2fma(cr, NEG1, ar);   Xi4[2] = f2fma(ci, NEG1, ai);
        Xr[3] = f2fma(di, NEG1, br);   Xi4[3] = add2(bi, dr);

        const float* fB = g_filt + (long)b * HF + (long)h * FB;
        const float* cB = g_bias + (long)b * HF + (long)h * FB;
        float oR[4][2], oI[4][2];
        #pragma unroll
        for (int p = 0; p < 4; p++) {
            float rr[2], ii[2];
            upk2(Xr[p], rr[0], rr[1]); upk2(Xi4[p], ii[0], ii[1]);
            int k2 = e + 12 * p;
            #pragma unroll
            for (int q = 0; q < 2; q++) {
                int k = k2 * 48 + c2 + q;
                int f = (k <= 1152) ? k : (2304 - k);
                float gf = fB[f], bbv = cB[f];
                float Fr = rr[q] * inv48, Fi = ii[q] * inv48;
                float mr = Fr * gf + bbv, mi = Fi * gf;
                float mag = sqrtf(mr * mr + mi * mi);
                float fac = 0.5f * mag * (1.0f + erff(mag * 0.70710678118654752f)) / (mag + 1e-6f);
                oR[p][q] = mr * fac; oI[p][q] = mi * fac;
            }
        }
        __syncthreads();   // bufA (x) dead -> reuse as Xr storage
        #pragma unroll
        for (int p = 0; p < 4; p++) {
            int k2 = e + 12 * p;
            *(u64*)&bufA[k2 * 52 + c2] = pk2(oR[p][0], oR[p][1]);
            *(u64*)&Xim [k2 * 52 + c2] = pk2(oI[p][0], oI[p][1]);
        }
    }
    __syncthreads();

    // ======== stage 3: inverse over k2 (complex), rows stride 52 ========
    {
        u64 S0r=0,S0i=0,S1r=0,S1i=0,S2r=0,S2i=0,S3r=0,S3i=0;
        int idx = 0;
        #pragma unroll 4
        for (int m = 0; m < 12; m++) {
            float2 w = w12[idx]; idx += e; if (idx >= 12) idx -= 12;
            u64 cc = pk2(w.x, w.x), ss = pk2(w.y, w.y), ns = pk2(-w.y, -w.y);
            u64 vr0 = *(const u64*)&bufA[(4*m+0)*52 + c2], vi0 = *(const u64*)&Xim[(4*m+0)*52 + c2];
            u64 vr1 = *(const u64*)&bufA[(4*m+1)*52 + c2], vi1 = *(const u64*)&Xim[(4*m+1)*52 + c2];
            u64 vr2 = *(const u64*)&bufA[(4*m+2)*52 + c2], vi2 = *(const u64*)&Xim[(4*m+2)*52 + c2];
            u64 vr3 = *(const u64*)&bufA[(4*m+3)*52 + c2], vi3 = *(const u64*)&Xim[(4*m+3)*52 + c2];
            S0r = f2fma(vr0, cc, S0r); S0r = f2fma(vi0, ns, S0r);
            S0i = f2fma(vi0, cc, S0i); S0i = f2fma(vr0, ss, S0i);
            S1r = f2fma(vr1, cc, S1r); S1r = f2fma(vi1, ns, S1r);
            S1i = f2fma(vi1, cc, S1i); S1i = f2fma(vr1, ss, S1i);
            S2r = f2fma(vr2, cc, S2r); S2r = f2fma(vi2, ns, S2r);
            S2i = f2fma(vi2, cc, S2i); S2i = f2fma(vr2, ss, S2i);
            S3r = f2fma(vr3, cc, S3r); S3r = f2fma(vi3, ns, S3r);
            S3i = f2fma(vi3, cc, S3i); S3i = f2fma(vr3, ss, S3i);
        }
        // inverse T = (c,+s)*S: Tr = Sr c - Si s ; Ti = Sr s + Si c
        u64 c1=pk2(we1.x,we1.x), s1=pk2(we1.y,we1.y), n1=pk2(-we1.y,-we1.y);
        u64 c2p=pk2(we2.x,we2.x), s2p=pk2(we2.y,we2.y), n2p=pk2(-we2.y,-we2.y);
        u64 c3=pk2(we3.x,we3.x), s3=pk2(we3.y,we3.y), n3=pk2(-we3.y,-we3.y);
        u64 T1r = f2fma(S1i, n1, mul2(S1r, c1)),  T1i = f2fma(S1r, s1, mul2(S1i, c1));
        u64 T2r = f2fma(S2i, n2p, mul2(S2r, c2p)), T2i = f2fma(S2r, s2p, mul2(S2i, c2p));
        u64 T3r = f2fma(S3i, n3, mul2(S3r, c3)),  T3i = f2fma(S3r, s3, mul2(S3i, c3));
        u64 ar = add2(S0r, T2r), ai = add2(S0i, T2i);
        u64 br = f2fma(T2r, NEG1, S0r), bi = f2fma(T2i, NEG1, S0i);
        u64 cr = add2(T1r, T3r), ci = add2(T1i, T3i);
        u64 dr = f2fma(T3r, NEG1, T1r), di = f2fma(T3i, NEG1, T1i);
        u64 Xr[4], Xi4[4];
        Xr[0] = add2(ar, cr);          Xi4[0] = add2(ai, ci);
        Xr[1] = f2fma(di, NEG1, br);   Xi4[1] = add2(bi, dr);          // b + i d
        Xr[2] = f2fma(cr, NEG1, ar);   Xi4[2] = f2fma(ci, NEG1, ai);
        Xr[3] = add2(br, di);          Xi4[3] = f2fma(dr, NEG1, bi);   // b - i d
        #pragma unroll
        for (int p = 0; p < 4; p++) {
            float r0, r1, i0, i1;
            upk2(Xr[p], r0, r1); upk2(Xi4[p], i0, i1);
            int r = e + 12 * p;
            float2 ta = g_tw[r * c2];
            wre[c2 * 52 + r]       = r0 * ta.x - i0 * ta.y;
            wim[c2 * 52 + r]       = r0 * ta.y + i0 * ta.x;
            float2 tb = g_tw[r * (c2 + 1)];
            wre[(c2 + 1) * 52 + r] = r1 * tb.x - i1 * tb.y;
            wim[(c2 + 1) * 52 + r] = r1 * tb.y + i1 * tb.x;
        }
    }
    __syncthreads();

    // ======== stage 4: inverse over k1 (complex in, real out), rows stride 52 ========
    {
        u64 S0r=0,S1r=0,S1i=0,S2r=0,S2i=0,S3r=0,S3i=0;
        int idx = 0;
        #pragma unroll 4
        for (int m = 0; m < 12; m++) {
            float2 w = w12[idx]; idx += e; if (idx >= 12) idx -= 12;
            u64 cc = pk2(w.x, w.x), ss = pk2(w.y, w.y), ns = pk2(-w.y, -w.y);
            u64 vr0 = *(const u64*)&wre[(4*m+0)*52 + c2], vi0 = *(const u64*)&wim[(4*m+0)*52 + c2];
            u64 vr1 = *(const u64*)&wre[(4*m+1)*52 + c2], vi1 = *(const u64*)&wim[(4*m+1)*52 + c2];
            u64 vr2 = *(const u64*)&wre[(4*m+2)*52 + c2], vi2 = *(const u64*)&wim[(4*m+2)*52 + c2];
            u64 vr3 = *(const u64*)&wre[(4*m+3)*52 + c2], vi3 = *(const u64*)&wim[(4*m+3)*52 + c2];
            S0r = f2fma(vr0, cc, S0r); S0r = f2fma(vi0, ns, S0r);
            S1r = f2fma(vr1, cc, S1r); S1r = f2fma(vi1, ns, S1r);
            S1i = f2fma(vi1, cc, S1i); S1i = f2fma(vr1, ss, S1i);
            S2r = f2fma(vr2, cc, S2r); S2r = f2fma(vi2, ns, S2r);
            S2i = f2fma(vi2, cc, S2i); S2i = f2fma(vr2, ss, S2i);
            S3r = f2fma(vr3, cc, S3r); S3r = f2fma(vi3, ns, S3r);
            S3i = f2fma(vi3, cc, S3i); S3i = f2fma(vr3, ss, S3i);
        }
        u64 c1=pk2(we1.x,we1.x), s1=pk2(we1.y,we1.y), n1=pk2(-we1.y,-we1.y);
        u64 c2p=pk2(we2.x,we2.x), n2p=pk2(-we2.y,-we2.y);
        u64 c3=pk2(we3.x,we3.x), s3=pk2(we3.y,we3.y), n3=pk2(-we3.y,-we3.y);
        u64 T1r = f2fma(S1i, n1, mul2(S1r, c1)),  T1i = f2fma(S1r, s1, mul2(S1i, c1));
        u64 T2r = f2fma(S2i, n2p, mul2(S2r, c2p));
        u64 T3r = f2fma(S3i, n3, mul2(S3r, c3)),  T3i = f2fma(S3r, s3, mul2(S3i, c3));
        u64 ar = add2(S0r, T2r);
        u64 br = f2fma(T2r, NEG1, S0r);
        u64 cr = add2(T1r, T3r);
        u64 di = f2fma(T3i, NEG1, T1i);
        u64 I48 = pk2(inv48, inv48);
        u64 y0 = mul2(add2(ar, cr), I48);             // q = e
        u64 y1 = mul2(f2fma(di, NEG1, br), I48);      // q = e+12 : Re(b + i d) = br - di
        u64 y2 = mul2(f2fma(cr, NEG1, ar), I48);      // q = e+24
        u64 y3 = mul2(add2(br, di), I48);             // q = e+36 : Re(b - i d) = br + di
        float* dst = g_yt + (long)col * NN;
        *(u64*)&dst[(e     ) * 48 + c2] = y0;
        *(u64*)&dst[(e + 12) * 48 + c2] = y1;
        *(u64*)&dst[(e + 24) * 48 + c2] = y2;
        *(u64*)&dst[(e + 36) * 48 + c2] = y3;
    }
}

// ---------------- output: out[b][n][d] = x + yt^T ----------------
__global__ void addout_kernel(const float* __restrict__ x, float* __restrict__ out) {
    __shared__ float tile[32][33];
    int b  = blockIdx.z;
    int n0 = blockIdx.x * 32;
    int d0 = blockIdx.y * 32;
    int tx = threadIdx.x, ty = threadIdx.y;
    const float* src = g_yt + ((long)b * DD + d0) * NN + n0;
    #pragma unroll
    for (int i = 0; i < 32; i += 8)
        tile[ty + i][tx] = src[(long)(ty + i) * NN + tx];
    __syncthreads();
    long base = ((long)b * NN + n0) * DD + d0;
    #pragma unroll
    for (int i = 0; i < 32; i += 8)
        out[base + (long)(ty + i) * DD + tx] =
            x[base + (long)(ty + i) * DD + tx] + tile[tx][ty + i];
}

// ---------------- launch ----------------
extern "C" void kernel_launch(void* const* d_in, const int* in_sizes, int n_in,
                              void* d_out, int out_size) {
    const float* x           = (const float*)d_in[0];
    const float* base_filter = (const float*)d_in[1];
    const float* base_bias   = (const float*)d_in[2];
    const float* ln_gamma    = (const float*)d_in[3];
    const float* ln_beta     = (const float*)d_in[4];
    const float* W1          = (const float*)d_in[5];
    const float* b1          = (const float*)d_in[6];
    const float* W2          = (const float*)d_in[7];
    const float* b2          = (const float*)d_in[8];
    float* out = (float*)d_out;

    init_kernel<<<32, 256>>>();
    ln_t_kernel<<<dim3(NN / 32, BB), 256>>>(x, ln_gamma, ln_beta);
    mlp1_kernel<<<dim3(BB, 4), 256>>>(W1, b1);
    mlp2_kernel<<<(OUT2 + 63) / 64, 256>>>(W2, b2, base_filter, base_bias);
    spectral_kernel<<<BB * DD, 288>>>();
    addout_kernel<<<dim3(NN / 32, DD / 32, BB), dim3(32, 8)>>>(x, out);
}

// round 7
// speedup vs baseline: 5.2484x; 1.0587x over previous
#include <cuda_runtime.h>
#include <cuda_bf16.h>

// Problem constants
#define BB   32
#define DD   256
#define NN   2304      // 48*48
#define HEADS 8
#define FB   1153      // NN/2+1
#define HF   (HEADS*FB)        // 9224
#define OUT2 (HEADS*FB*2)      // 18448

#define MLP2_SMEM ((DD*BB + 3*256*8) * 4)   // 32KB + 24KB = 57344 bytes

// ---------------- scratch ----------------
__device__ float  g_xh   [BB*DD*NN];   // [b][d][n]
__device__ float  g_yt   [BB*DD*NN];   // filtered, [b][d][n]
__device__ float  g_ctx  [BB*DD];      // raw sums (atomic), scaled in mlp1
__device__ float  g_hmidT[DD*BB];      // transposed: [o][b]
__device__ float  g_filt [BB*HF];
__device__ float  g_bias [BB*HF];
__device__ float2 g_tw   [NN];         // (cos, sin)(2*pi*j/2304)

typedef unsigned long long u64;

// ---------------- packed f32x2 helpers ----------------
__device__ __forceinline__ u64 pk2(float lo, float hi) {
    u64 r; asm("mov.b64 %0, {%1,%2};" : "=l"(r) : "f"(lo), "f"(hi)); return r;
}
__device__ __forceinline__ void upk2(u64 v, float& lo, float& hi) {
    asm("mov.b64 {%0,%1}, %2;" : "=f"(lo), "=f"(hi) : "l"(v));
}
__device__ __forceinline__ u64 f2fma(u64 a, u64 b, u64 c) {
    u64 d; asm("fma.rn.f32x2 %0, %1, %2, %3;" : "=l"(d) : "l"(a), "l"(b), "l"(c)); return d;
}
__device__ __forceinline__ u64 add2(u64 a, u64 b) {
    u64 d; asm("add.rn.f32x2 %0, %1, %2;" : "=l"(d) : "l"(a), "l"(b)); return d;
}
__device__ __forceinline__ u64 mul2(u64 a, u64 b) {
    u64 d; asm("mul.rn.f32x2 %0, %1, %2;" : "=l"(d) : "l"(a), "l"(b)); return d;
}

// ---------------- init: twiddles + zero ctx ----------------
__global__ void init_kernel() {
    int j = blockIdx.x * blockDim.x + threadIdx.x;   // 8192 threads
    if (j < NN) {
        float sv, cv;
        sincospif((float)j * (1.0f / 1152.0f), &sv, &cv);
        g_tw[j] = make_float2(cv, sv);
    }
    g_ctx[j] = 0.f;
}

// ---------------- fused LayerNorm + transpose + ctx partials ----------------
__global__ __launch_bounds__(256) void ln_t_kernel(const float* __restrict__ x,
                                                   const float* __restrict__ gamma,
                                                   const float* __restrict__ beta) {
    __shared__ float tile[32 * 257];
    __shared__ float smu[32], srs[32];
    int b  = blockIdx.y;
    int n0 = blockIdx.x * 32;
    int t  = threadIdx.x;

    const float* src = x + ((long)b * NN + n0) * DD;
    #pragma unroll
    for (int l = t; l < 32 * DD; l += 256) {
        int r = l >> 8, d = l & 255;
        tile[r * 257 + d] = src[l];
    }
    __syncthreads();

    int w = t >> 5, lane = t & 31;
    #pragma unroll
    for (int r = w; r < 32; r += 8) {
        float s = 0.f, s2 = 0.f;
        #pragma unroll
        for (int j = 0; j < 8; j++) {
            float v = tile[r * 257 + lane + j * 32];
            s += v; s2 += v * v;
        }
        #pragma unroll
        for (int o = 16; o; o >>= 1) {
            s  += __shfl_xor_sync(0xffffffffu, s, o);
            s2 += __shfl_xor_sync(0xffffffffu, s2, o);
        }
        if (lane == 0) {
            float mu = s * (1.0f / 256.0f);
            smu[r] = mu;
            srs[r] = rsqrtf(s2 * (1.0f / 256.0f) - mu * mu + 1e-5f);
        }
    }
    __syncthreads();

    #pragma unroll
    for (int l = t; l < 32 * DD; l += 256) {
        int d = l >> 5, i = l & 31;   // d is warp-uniform
        float v = (tile[i * 257 + d] - smu[i]) * srs[i] * gamma[d] + beta[d];
        g_xh[((long)b * DD + d) * NN + n0 + i] = v;
        float sv = v;
        #pragma unroll
        for (int o = 16; o; o >>= 1) sv += __shfl_xor_sync(0xffffffffu, sv, o);
        if (lane == 0) atomicAdd(&g_ctx[b * DD + d], sv);
    }
}

// ---------------- MLP layer 1 (8-way split-K, 512 thr) -> hmidT ----------------
__global__ __launch_bounds__(512) void mlp1_kernel(const float* __restrict__ W1,
                                                   const float* __restrict__ b1) {
    __shared__ float sc[DD];
    __shared__ float part[8][64];
    int b = blockIdx.x, o0 = blockIdx.y * 64;
    int t = threadIdx.x;
    if (t < DD) sc[t] = g_ctx[b * DD + t] * (1.0f / NN);
    __syncthreads();
    int ol = t & 63, kp = t >> 6;     // kp 0..7
    int o = o0 + ol;
    float acc = 0.f;
    #pragma unroll 8
    for (int d = kp * 32; d < kp * 32 + 32; d++) acc += sc[d] * W1[d * DD + o];
    part[kp][ol] = acc;
    __syncthreads();
    if (t < 64) {
        float a = b1[o0 + t];
        #pragma unroll
        for (int p = 0; p < 8; p++) a += part[p][t];
        g_hmidT[(o0 + t) * BB + b] = 0.5f * a * (1.0f + erff(a * 0.70710678118654752f));
    }
}

// ---------------- MLP layer 2 (batched over b, 4-way split-K, 1024 thr, dyn smem) ----------------
__global__ __launch_bounds__(1024) void mlp2_kernel(const float* __restrict__ W2,
                                                    const float* __restrict__ b2,
                                                    const float* __restrict__ base_filter,
                                                    const float* __restrict__ base_bias) {
    extern __shared__ float dynsm[];
    float* sh   = dynsm;                 // hmidT copy: [j][b]   (32 KB)
    float* part = dynsm + DD * BB;       // partials for kp=1..3 (24 KB)
    int t = threadIdx.x;
    #pragma unroll
    for (int i = t; i < DD * BB; i += 1024) sh[i] = g_hmidT[i];
    __syncthreads();

    int ol = t & 63, bg = (t >> 6) & 3, kp = t >> 8;   // kp 0..3
    int o = blockIdx.x * 64 + ol;
    bool valid = (o < OUT2);
    int b0 = bg * 8;

    u64 acc0 = 0, acc1 = 0, acc2 = 0, acc3 = 0;
    if (valid) {
        #pragma unroll 4
        for (int j = kp * 64; j < kp * 64 + 64; j++) {
            float wv = W2[(long)j * OUT2 + o];
            u64 wp = pk2(wv, wv);
            const u64* hp = (const u64*)&sh[j * BB + b0];
            acc0 = f2fma(hp[0], wp, acc0);
            acc1 = f2fma(hp[1], wp, acc1);
            acc2 = f2fma(hp[2], wp, acc2);
            acc3 = f2fma(hp[3], wp, acc3);
        }
    }
    if (kp > 0) {
        u64* pp = (u64*)&part[((kp - 1) * 256 + (t & 255)) * 8];
        pp[0] = acc0; pp[1] = acc1; pp[2] = acc2; pp[3] = acc3;
    }
    __syncthreads();
    if (kp == 0 && valid) {
        #pragma unroll
        for (int p = 0; p < 3; p++) {
            const u64* pp = (const u64*)&part[(p * 256 + (t & 255)) * 8];
            acc0 = add2(acc0, pp[0]);
            acc1 = add2(acc1, pp[1]);
            acc2 = add2(acc2, pp[2]);
            acc3 = add2(acc3, pp[3]);
        }
        float a[8];
        upk2(acc0, a[0], a[1]); upk2(acc1, a[2], a[3]);
        upk2(acc2, a[4], a[5]); upk2(acc3, a[6], a[7]);
        float bias2 = b2[o];
        int idx2 = o >> 1;
        if ((o & 1) == 0) {
            float base = base_filter[idx2];
            #pragma unroll
            for (int r = 0; r < 8; r++)
                g_filt[(long)(b0 + r) * HF + idx2] = base * (1.0f + a[r] + bias2);
        } else {
            float base = base_bias[idx2];
            #pragma unroll
            for (int r = 0; r < 8; r++)
                g_bias[(long)(b0 + r) * HF + idx2] = base + a[r] + bias2;
        }
    }
}

// ---------------- spectral kernel: radix-4 (48 = 4x12), packed f32x2 ----------------
// 288 threads: e = t%12 (outputs e, e+12, e+24, e+36), g = t/12 -> cols c2 = 2g, 2g+1
__global__ __launch_bounds__(288) void spectral_kernel() {
    __shared__ float sm[120 + 4 * 2496];
    float2* w12 = (float2*)sm;             // 12 entries @ [0,24)
    float2* w48 = (float2*)(sm + 24);      // 48 entries @ [24,120)
    float*  bufA = sm + 120;               // 2496: x (stride 48), later Xr (stride 52)
    float*  Xim  = bufA + 2496;
    float*  wre  = Xim + 2496;
    float*  wim  = wre + 2496;

    int col = blockIdx.x;
    int b = col >> 8, d = col & 255, h = d >> 5;
    int t = threadIdx.x;
    int e  = t % 12;
    int c2 = (t / 12) * 2;
    const float inv48 = 1.0f / 48.0f;
    const u64 NEG1 = pk2(-1.0f, -1.0f);

    if (t < 12) w12[t] = g_tw[192 * t];
    else if (t < 60) w48[t - 12] = g_tw[48 * (t - 12)];
    const float* src = g_xh + (long)col * NN;
    for (int i = t; i < NN; i += 288) bufA[i] = src[i];
    __syncthreads();

    float2 we1 = w48[e], we2 = w48[2 * e], we3 = w48[3 * e];

    // ======== stage 1: forward over n1 (real input), rows stride 48 ========
    {
        u64 S0r=0,S0i=0,S1r=0,S1i=0,S2r=0,S2i=0,S3r=0,S3i=0;
        int idx = 0;
        #pragma unroll
        for (int m = 0; m < 12; m++) {
            float2 w = w12[idx]; idx += e; if (idx >= 12) idx -= 12;
            u64 cc = pk2(w.x, w.x), ns = pk2(-w.y, -w.y);
            u64 v0 = *(const u64*)&bufA[(4*m+0)*48 + c2];
            u64 v1 = *(const u64*)&bufA[(4*m+1)*48 + c2];
            u64 v2 = *(const u64*)&bufA[(4*m+2)*48 + c2];
            u64 v3 = *(const u64*)&bufA[(4*m+3)*48 + c2];
            S0r = f2fma(v0, cc, S0r); S0i = f2fma(v0, ns, S0i);
            S1r = f2fma(v1, cc, S1r); S1i = f2fma(v1, ns, S1i);
            S2r = f2fma(v2, cc, S2r); S2i = f2fma(v2, ns, S2i);
            S3r = f2fma(v3, cc, S3r); S3i = f2fma(v3, ns, S3i);
        }
        // forward T = (c,-s)*S:  Tr = Sr c + Si s ; Ti = Si c - Sr s
        u64 c1=pk2(we1.x,we1.x), s1=pk2(we1.y,we1.y), n1=pk2(-we1.y,-we1.y);
        u64 c2p=pk2(we2.x,we2.x), s2p=pk2(we2.y,we2.y), n2p=pk2(-we2.y,-we2.y);
        u64 c3=pk2(we3.x,we3.x), s3=pk2(we3.y,we3.y), n3=pk2(-we3.y,-we3.y);
        u64 T1r = f2fma(S1i, s1, mul2(S1r, c1)),  T1i = f2fma(S1r, n1, mul2(S1i, c1));
        u64 T2r = f2fma(S2i, s2p, mul2(S2r, c2p)), T2i = f2fma(S2r, n2p, mul2(S2i, c2p));
        u64 T3r = f2fma(S3i, s3, mul2(S3r, c3)),  T3i = f2fma(S3r, n3, mul2(S3i, c3));
        u64 ar = add2(S0r, T2r), ai = add2(S0i, T2i);
        u64 br = f2fma(T2r, NEG1, S0r), bi = f2fma(T2i, NEG1, S0i);
        u64 cr = add2(T1r, T3r), ci = add2(T1i, T3i);
        u64 dr = f2fma(T3r, NEG1, T1r), di = f2fma(T3i, NEG1, T1i);
        u64 Xr[4], Xi4[4];
        Xr[0] = add2(ar, cr);          Xi4[0] = add2(ai, ci);
        Xr[1] = add2(br, di);          Xi4[1] = f2fma(dr, NEG1, bi);   // b - i d
        Xr[2] = f2fma(cr, NEG1, ar);   Xi4[2] = f2fma(ci, NEG1, ai);
        Xr[3] = f2fma(di, NEG1, br);   Xi4[3] = add2(bi, dr);          // b + i d
        #pragma unroll
        for (int p = 0; p < 4; p++) {
            float r0, r1, i0, i1;
            upk2(Xr[p], r0, r1); upk2(Xi4[p], i0, i1);
            int k = e + 12 * p;
            float2 ta = g_tw[k * c2];
            wre[c2 * 52 + k]       = r0 * ta.x + i0 * ta.y;
            wim[c2 * 52 + k]       = i0 * ta.x - r0 * ta.y;
            float2 tb = g_tw[k * (c2 + 1)];
            wre[(c2 + 1) * 52 + k] = r1 * tb.x + i1 * tb.y;
            wim[(c2 + 1) * 52 + k] = i1 * tb.x - r1 * tb.y;
        }
    }
    __syncthreads();

    // ======== stage 2: forward over n2 (complex), rows stride 52; modulate ========
    {
        u64 S0r=0,S0i=0,S1r=0,S1i=0,S2r=0,S2i=0,S3r=0,S3i=0;
        int idx = 0;
        #pragma unroll
        for (int m = 0; m < 12; m++) {
            float2 w = w12[idx]; idx += e; if (idx >= 12) idx -= 12;
            u64 cc = pk2(w.x, w.x), ss = pk2(w.y, w.y), ns = pk2(-w.y, -w.y);
            u64 vr0 = *(const u64*)&wre[(4*m+0)*52 + c2], vi0 = *(const u64*)&wim[(4*m+0)*52 + c2];
            u64 vr1 = *(const u64*)&wre[(4*m+1)*52 + c2], vi1 = *(const u64*)&wim[(4*m+1)*52 + c2];
            u64 vr2 = *(const u64*)&wre[(4*m+2)*52 + c2], vi2 = *(const u64*)&wim[(4*m+2)*52 + c2];
            u64 vr3 = *(const u64*)&wre[(4*m+3)*52 + c2], vi3 = *(const u64*)&wim[(4*m+3)*52 + c2];
            S0r = f2fma(vr0, cc, S0r); S0r = f2fma(vi0, ss, S0r);
            S0i = f2fma(vi0, cc, S0i); S0i = f2fma(vr0, ns, S0i);
            S1r = f2fma(vr1, cc, S1r); S1r = f2fma(vi1, ss, S1r);
            S1i = f2fma(vi1, cc, S1i); S1i = f2fma(vr1, ns, S1i);
            S2r = f2fma(vr2, cc, S2r); S2r = f2fma(vi2, ss, S2r);
            S2i = f2fma(vi2, cc, S2i); S2i = f2fma(vr2, ns, S2i);
            S3r = f2fma(vr3, cc, S3r); S3r = f2fma(vi3, ss, S3r);
            S3i = f2fma(vi3, cc, S3i); S3i = f2fma(vr3, ns, S3i);
        }
        u64 c1=pk2(we1.x,we1.x), s1=pk2(we1.y,we1.y), n1=pk2(-we1.y,-we1.y);
        u64 c2p=pk2(we2.x,we2.x), s2p=pk2(we2.y,we2.y), n2p=pk2(-we2.y,-we2.y);
        u64 c3=pk2(we3.x,we3.x), s3=pk2(we3.y,we3.y), n3=pk2(-we3.y,-we3.y);
        u64 T1r = f2fma(S1i, s1, mul2(S1r, c1)),  T1i = f2fma(S1r, n1, mul2(S1i, c1));
        u64 T2r = f2fma(S2i, s2p, mul2(S2r, c2p)), T2i = f2fma(S2r, n2p, mul2(S2i, c2p));
        u64 T3r = f2fma(S3i, s3, mul2(S3r, c3)),  T3i = f2fma(S3r, n3, mul2(S3i, c3));
        u64 ar = add2(S0r, T2r), ai = add2(S0i, T2i);
        u64 br = f2fma(T2r, NEG1, S0r), bi = f2fma(T2i, NEG1, S0i);
        u64 cr = add2(T1r, T3r), ci = add2(T1i, T3i);
        u64 dr = f2fma(T3r, NEG1, T1r), di = f2fma(T3i, NEG1, T1i);
        u64 Xr[4], Xi4[4];
        Xr[0] = add2(ar, cr);          Xi4[0] = add2(ai, ci);
        Xr[1] = add2(br, di);          Xi4[1] = f2fma(dr, NEG1, bi);
        Xr[2] = f2fma(cr, NEG1, ar);   Xi4[2] = f2fma(ci, NEG1, ai);
        Xr[3] = f2fma(di, NEG1, br);   Xi4[3] = add2(bi, dr);

        const float* fB = g_filt + (long)b * HF + (long)h * FB;
        const float* cB = g_bias + (long)b * HF + (long)h * FB;
        float oR[4][2], oI[4][2];
        #pragma unroll
        for (int p = 0; p < 4; p++) {
            float rr[2], ii[2];
            upk2(Xr[p], rr[0], rr[1]); upk2(Xi4[p], ii[0], ii[1]);
            int k2 = e + 12 * p;
            #pragma unroll
            for (int q = 0; q < 2; q++) {
                int k = k2 * 48 + c2 + q;
                int f = (k <= 1152) ? k : (2304 - k);
                float gf = fB[f], bbv = cB[f];
                float Fr = rr[q] * inv48, Fi = ii[q] * inv48;
                float mr = Fr * gf + bbv, mi = Fi * gf;
                float mag = sqrtf(mr * mr + mi * mi);
                float fac = 0.5f * mag * (1.0f + erff(mag * 0.70710678118654752f)) / (mag + 1e-6f);
                oR[p][q] = mr * fac; oI[p][q] = mi * fac;
            }
        }
        __syncthreads();   // bufA (x) dead -> reuse as Xr storage
        #pragma unroll
        for (int p = 0; p < 4; p++) {
            int k2 = e + 12 * p;
            *(u64*)&bufA[k2 * 52 + c2] = pk2(oR[p][0], oR[p][1]);
            *(u64*)&Xim [k2 * 52 + c2] = pk2(oI[p][0], oI[p][1]);
        }
    }
    __syncthreads();

    // ======== stage 3: inverse over k2 (complex), rows stride 52 ========
    {
        u64 S0r=0,S0i=0,S1r=0,S1i=0,S2r=0,S2i=0,S3r=0,S3i=0;
        int idx = 0;
        #pragma unroll
        for (int m = 0; m < 12; m++) {
            float2 w = w12[idx]; idx += e; if (idx >= 12) idx -= 12;
            u64 cc = pk2(w.x, w.x), ss = pk2(w.y, w.y), ns = pk2(-w.y, -w.y);
            u64 vr0 = *(const u64*)&bufA[(4*m+0)*52 + c2], vi0 = *(const u64*)&Xim[(4*m+0)*52 + c2];
            u64 vr1 = *(const u64*)&bufA[(4*m+1)*52 + c2], vi1 = *(const u64*)&Xim[(4*m+1)*52 + c2];
            u64 vr2 = *(const u64*)&bufA[(4*m+2)*52 + c2], vi2 = *(const u64*)&Xim[(4*m+2)*52 + c2];
            u64 vr3 = *(const u64*)&bufA[(4*m+3)*52 + c2], vi3 = *(const u64*)&Xim[(4*m+3)*52 + c2];
            S0r = f2fma(vr0, cc, S0r); S0r = f2fma(vi0, ns, S0r);
            S0i = f2fma(vi0, cc, S0i); S0i = f2fma(vr0, ss, S0i);
            S1r = f2fma(vr1, cc, S1r); S1r = f2fma(vi1, ns, S1r);
            S1i = f2fma(vi1, cc, S1i); S1i = f2fma(vr1, ss, S1i);
            S2r = f2fma(vr2, cc, S2r); S2r = f2fma(vi2, ns, S2r);
            S2i = f2fma(vi2, cc, S2i); S2i = f2fma(vr2, ss, S2i);
            S3r = f2fma(vr3, cc, S3r); S3r = f2fma(vi3, ns, S3r);
            S3i = f2fma(vi3, cc, S3i); S3i = f2fma(vr3, ss, S3i);
        }
        // inverse T = (c,+s)*S: Tr = Sr c - Si s ; Ti = Sr s + Si c
        u64 c1=pk2(we1.x,we1.x), s1=pk2(we1.y,we1.y), n1=pk2(-we1.y,-we1.y);
        u64 c2p=pk2(we2.x,we2.x), s2p=pk2(we2.y,we2.y), n2p=pk2(-we2.y,-we2.y);
        u64 c3=pk2(we3.x,we3.x), s3=pk2(we3.y,we3.y), n3=pk2(-we3.y,-we3.y);
        u64 T1r = f2fma(S1i, n1, mul2(S1r, c1)),  T1i = f2fma(S1r, s1, mul2(S1i, c1));
        u64 T2r = f2fma(S2i, n2p, mul2(S2r, c2p)), T2i = f2fma(S2r, s2p, mul2(S2i, c2p));
        u64 T3r = f2fma(S3i, n3, mul2(S3r, c3)),  T3i = f2fma(S3r, s3, mul2(S3i, c3));
        u64 ar = add2(S0r, T2r), ai = add2(S0i, T2i);
        u64 br = f2fma(T2r, NEG1, S0r), bi = f2fma(T2i, NEG1, S0i);
        u64 cr = add2(T1r, T3r), ci = add2(T1i, T3i);
        u64 dr = f2fma(T3r, NEG1, T1r), di = f2fma(T3i, NEG1, T1i);
        u64 Xr[4], Xi4[4];
        Xr[0] = add2(ar, cr);          Xi4[0] = add2(ai, ci);
        Xr[1] = f2fma(di, NEG1, br);   Xi4[1] = add2(bi, dr);          // b + i d
        Xr[2] = f2fma(cr, NEG1, ar);   Xi4[2] = f2fma(ci, NEG1, ai);
        Xr[3] = add2(br, di);          Xi4[3] = f2fma(dr, NEG1, bi);   // b - i d
        #pragma unroll
        for (int p = 0; p < 4; p++) {
            float r0, r1, i0, i1;
            upk2(Xr[p], r0, r1); upk2(Xi4[p], i0, i1);
            int r = e + 12 * p;
            float2 ta = g_tw[r * c2];
            wre[c2 * 52 + r]       = r0 * ta.x - i0 * ta.y;
            wim[c2 * 52 + r]       = r0 * ta.y + i0 * ta.x;
            float2 tb = g_tw[r * (c2 + 1)];
            wre[(c2 + 1) * 52 + r] = r1 * tb.x - i1 * tb.y;
            wim[(c2 + 1) * 52 + r] = r1 * tb.y + i1 * tb.x;
        }
    }
    __syncthreads();

    // ======== stage 4: inverse over k1 (complex in, real out), rows stride 52 ========
    {
        u64 S0r=0,S1r=0,S1i=0,S2r=0,S2i=0,S3r=0,S3i=0;
        int idx = 0;
        #pragma unroll
        for (int m = 0; m < 12; m++) {
            float2 w = w12[idx]; idx += e; if (idx >= 12) idx -= 12;
            u64 cc = pk2(w.x, w.x), ss = pk2(w.y, w.y), ns = pk2(-w.y, -w.y);
            u64 vr0 = *(const u64*)&wre[(4*m+0)*52 + c2], vi0 = *(const u64*)&wim[(4*m+0)*52 + c2];
            u64 vr1 = *(const u64*)&wre[(4*m+1)*52 + c2], vi1 = *(const u64*)&wim[(4*m+1)*52 + c2];
            u64 vr2 = *(const u64*)&wre[(4*m+2)*52 + c2], vi2 = *(const u64*)&wim[(4*m+2)*52 + c2];
            u64 vr3 = *(const u64*)&wre[(4*m+3)*52 + c2], vi3 = *(const u64*)&wim[(4*m+3)*52 + c2];
            S0r = f2fma(vr0, cc, S0r); S0r = f2fma(vi0, ns, S0r);
            S1r = f2fma(vr1, cc, S1r); S1r = f2fma(vi1, ns, S1r);
            S1i = f2fma(vi1, cc, S1i); S1i = f2fma(vr1, ss, S1i);
            S2r = f2fma(vr2, cc, S2r); S2r = f2fma(vi2, ns, S2r);
            S2i = f2fma(vi2, cc, S2i); S2i = f2fma(vr2, ss, S2i);
            S3r = f2fma(vr3, cc, S3r); S3r = f2fma(vi3, ns, S3r);
            S3i = f2fma(vi3, cc, S3i); S3i = f2fma(vr3, ss, S3i);
        }
        u64 c1=pk2(we1.x,we1.x), s1=pk2(we1.y,we1.y), n1=pk2(-we1.y,-we1.y);
        u64 c2p=pk2(we2.x,we2.x), n2p=pk2(-we2.y,-we2.y);
        u64 c3=pk2(we3.x,we3.x), s3=pk2(we3.y,we3.y), n3=pk2(-we3.y,-we3.y);
        u64 T1r = f2fma(S1i, n1, mul2(S1r, c1)),  T1i = f2fma(S1r, s1, mul2(S1i, c1));
        u64 T2r = f2fma(S2i, n2p, mul2(S2r, c2p));
        u64 T3r = f2fma(S3i, n3, mul2(S3r, c3)),  T3i = f2fma(S3r, s3, mul2(S3i, c3));
        u64 ar = add2(S0r, T2r);
        u64 br = f2fma(T2r, NEG1, S0r);
        u64 cr = add2(T1r, T3r);
        u64 di = f2fma(T3i, NEG1, T1i);
        u64 I48 = pk2(inv48, inv48);
        u64 y0 = mul2(add2(ar, cr), I48);             // q = e
        u64 y1 = mul2(f2fma(di, NEG1, br), I48);      // q = e+12 : Re(b + i d) = br - di
        u64 y2 = mul2(f2fma(cr, NEG1, ar), I48);      // q = e+24
        u64 y3 = mul2(add2(br, di), I48);             // q = e+36 : Re(b - i d) = br + di
        float* dst = g_yt + (long)col * NN;
        *(u64*)&dst[(e     ) * 48 + c2] = y0;
        *(u64*)&dst[(e + 12) * 48 + c2] = y1;
        *(u64*)&dst[(e + 24) * 48 + c2] = y2;
        *(u64*)&dst[(e + 36) * 48 + c2] = y3;
    }
}

// ---------------- output: out[b][n][d] = x + yt^T ----------------
__global__ void addout_kernel(const float* __restrict__ x, float* __restrict__ out) {
    __shared__ float tile[32][33];
    int b  = blockIdx.z;
    int n0 = blockIdx.x * 32;
    int d0 = blockIdx.y * 32;
    int tx = threadIdx.x, ty = threadIdx.y;
    const float* src = g_yt + ((long)b * DD + d0) * NN + n0;
    #pragma unroll
    for (int i = 0; i < 32; i += 8)
        tile[ty + i][tx] = src[(long)(ty + i) * NN + tx];
    __syncthreads();
    long base = ((long)b * NN + n0) * DD + d0;
    #pragma unroll
    for (int i = 0; i < 32; i += 8)
        out[base + (long)(ty + i) * DD + tx] =
            x[base + (long)(ty + i) * DD + tx] + tile[tx][ty + i];
}

// ---------------- launch ----------------
extern "C" void kernel_launch(void* const* d_in, const int* in_sizes, int n_in,
                              void* d_out, int out_size) {
    const float* x           = (const float*)d_in[0];
    const float* base_filter = (const float*)d_in[1];
    const float* base_bias   = (const float*)d_in[2];
    const float* ln_gamma    = (const float*)d_in[3];
    const float* ln_beta     = (const float*)d_in[4];
    const float* W1          = (const float*)d_in[5];
    const float* b1          = (const float*)d_in[6];
    const float* W2          = (const float*)d_in[7];
    const float* b2          = (const float*)d_in[8];
    float* out = (float*)d_out;

    static bool attr_done = false;
    if (!attr_done) {
        cudaFuncSetAttribute(mlp2_kernel,
                             cudaFuncAttributeMaxDynamicSharedMemorySize, MLP2_SMEM);
        attr_done = true;
    }

    init_kernel<<<32, 256>>>();
    ln_t_kernel<<<dim3(NN / 32, BB), 256>>>(x, ln_gamma, ln_beta);
    mlp1_kernel<<<dim3(BB, 4), 512>>>(W1, b1);
    mlp2_kernel<<<(OUT2 + 63) / 64, 1024, MLP2_SMEM>>>(W2, b2, base_filter, base_bias);
    spectral_kernel<<<BB * DD, 288>>>();
    addout_kernel<<<dim3(NN / 32, DD / 32, BB), dim3(32, 8)>>>(x, out);
}

// round 8
// speedup vs baseline: 7.5827x; 1.4448x over previous
#include <cuda_runtime.h>
#include <cuda_bf16.h>

// Problem constants
#define BB   32
#define DD   256
#define NN   2304      // 48*48
#define HEADS 8
#define FB   1153      // NN/2+1
#define HF   (HEADS*FB)        // 9224
#define OUT2 (HEADS*FB*2)      // 18448

#define MLP2_SMEM ((DD*BB + 3*256*8) * 4)   // 57344 bytes

// ---------------- scratch ----------------
__device__ float  g_xh   [BB*DD*NN];   // [b][d][n]
__device__ float  g_yt   [BB*DD*NN];   // filtered, [b][d][n]
__device__ float  g_ctx  [BB*DD];      // raw sums (atomic), scaled in mlp1
__device__ float  g_hmidT[DD*BB];      // transposed: [o][b]
__device__ float  g_filt [BB*HF];
__device__ float  g_bias [BB*HF];
__device__ float2 g_tw   [NN];         // (cos, sin)(2*pi*j/2304)

typedef unsigned long long u64;

// ---------------- packed f32x2 helpers ----------------
__device__ __forceinline__ u64 pk2(float lo, float hi) {
    u64 r; asm("mov.b64 %0, {%1,%2};" : "=l"(r) : "f"(lo), "f"(hi)); return r;
}
__device__ __forceinline__ void upk2(u64 v, float& lo, float& hi) {
    asm("mov.b64 {%0,%1}, %2;" : "=f"(lo), "=f"(hi) : "l"(v));
}
__device__ __forceinline__ u64 f2fma(u64 a, u64 b, u64 c) {
    u64 d; asm("fma.rn.f32x2 %0, %1, %2, %3;" : "=l"(d) : "l"(a), "l"(b), "l"(c)); return d;
}
__device__ __forceinline__ u64 add2(u64 a, u64 b) {
    u64 d; asm("add.rn.f32x2 %0, %1, %2;" : "=l"(d) : "l"(a), "l"(b)); return d;
}
__device__ __forceinline__ u64 mul2(u64 a, u64 b) {
    u64 d; asm("mul.rn.f32x2 %0, %1, %2;" : "=l"(d) : "l"(a), "l"(b)); return d;
}

// ---------------- init: twiddles + zero ctx ----------------
__global__ void init_kernel() {
    int j = blockIdx.x * blockDim.x + threadIdx.x;   // 8192 threads
    if (j < NN) {
        float sv, cv;
        sincospif((float)j * (1.0f / 1152.0f), &sv, &cv);
        g_tw[j] = make_float2(cv, sv);
    }
    g_ctx[j] = 0.f;
}

// ---------------- fused LayerNorm + transpose + ctx partials ----------------
__global__ __launch_bounds__(256) void ln_t_kernel(const float* __restrict__ x,
                                                   const float* __restrict__ gamma,
                                                   const float* __restrict__ beta) {
    __shared__ float tile[32 * 257];
    __shared__ float smu[32], srs[32];
    int b  = blockIdx.y;
    int n0 = blockIdx.x * 32;
    int t  = threadIdx.x;

    const float* src = x + ((long)b * NN + n0) * DD;
    #pragma unroll
    for (int l = t; l < 32 * DD; l += 256) {
        int r = l >> 8, d = l & 255;
        tile[r * 257 + d] = src[l];
    }
    __syncthreads();

    int w = t >> 5, lane = t & 31;
    #pragma unroll
    for (int r = w; r < 32; r += 8) {
        float s = 0.f, s2 = 0.f;
        #pragma unroll
        for (int j = 0; j < 8; j++) {
            float v = tile[r * 257 + lane + j * 32];
            s += v; s2 += v * v;
        }
        #pragma unroll
        for (int o = 16; o; o >>= 1) {
            s  += __shfl_xor_sync(0xffffffffu, s, o);
            s2 += __shfl_xor_sync(0xffffffffu, s2, o);
        }
        if (lane == 0) {
            float mu = s * (1.0f / 256.0f);
            smu[r] = mu;
            srs[r] = rsqrtf(s2 * (1.0f / 256.0f) - mu * mu + 1e-5f);
        }
    }
    __syncthreads();

    #pragma unroll
    for (int l = t; l < 32 * DD; l += 256) {
        int d = l >> 5, i = l & 31;   // d is warp-uniform
        float v = (tile[i * 257 + d] - smu[i]) * srs[i] * gamma[d] + beta[d];
        g_xh[((long)b * DD + d) * NN + n0 + i] = v;
        float sv = v;
        #pragma unroll
        for (int o = 16; o; o >>= 1) sv += __shfl_xor_sync(0xffffffffu, sv, o);
        if (lane == 0) atomicAdd(&g_ctx[b * DD + d], sv);
    }
}

// ---------------- MLP layer 1 (8-way split-K, 512 thr) -> hmidT ----------------
__global__ __launch_bounds__(512) void mlp1_kernel(const float* __restrict__ W1,
                                                   const float* __restrict__ b1) {
    __shared__ float sc[DD];
    __shared__ float part[8][64];
    int b = blockIdx.x, o0 = blockIdx.y * 64;
    int t = threadIdx.x;
    if (t < DD) sc[t] = g_ctx[b * DD + t] * (1.0f / NN);
    __syncthreads();
    int ol = t & 63, kp = t >> 6;     // kp 0..7
    int o = o0 + ol;
    float acc = 0.f;
    #pragma unroll 8
    for (int d = kp * 32; d < kp * 32 + 32; d++) acc += sc[d] * W1[d * DD + o];
    part[kp][ol] = acc;
    __syncthreads();
    if (t < 64) {
        float a = b1[o0 + t];
        #pragma unroll
        for (int p = 0; p < 8; p++) a += part[p][t];
        g_hmidT[(o0 + t) * BB + b] = 0.5f * a * (1.0f + erff(a * 0.70710678118654752f));
    }
}

// ---------------- MLP layer 2 (batched over b, 4-way split-K, 1024 thr, dyn smem) ----------------
__global__ __launch_bounds__(1024) void mlp2_kernel(const float* __restrict__ W2,
                                                    const float* __restrict__ b2,
                                                    const float* __restrict__ base_filter,
                                                    const float* __restrict__ base_bias) {
    extern __shared__ float dynsm[];
    float* sh   = dynsm;                 // hmidT copy: [j][b]   (32 KB)
    float* part = dynsm + DD * BB;       // partials for kp=1..3 (24 KB)
    int t = threadIdx.x;
    #pragma unroll
    for (int i = t; i < DD * BB; i += 1024) sh[i] = g_hmidT[i];
    __syncthreads();

    int ol = t & 63, bg = (t >> 6) & 3, kp = t >> 8;   // kp 0..3
    int o = blockIdx.x * 64 + ol;
    bool valid = (o < OUT2);
    int b0 = bg * 8;

    u64 acc0 = 0, acc1 = 0, acc2 = 0, acc3 = 0;
    if (valid) {
        #pragma unroll 4
        for (int j = kp * 64; j < kp * 64 + 64; j++) {
            float wv = W2[(long)j * OUT2 + o];
            u64 wp = pk2(wv, wv);
            const u64* hp = (const u64*)&sh[j * BB + b0];
            acc0 = f2fma(hp[0], wp, acc0);
            acc1 = f2fma(hp[1], wp, acc1);
            acc2 = f2fma(hp[2], wp, acc2);
            acc3 = f2fma(hp[3], wp, acc3);
        }
    }
    if (kp > 0) {
        u64* pp = (u64*)&part[((kp - 1) * 256 + (t & 255)) * 8];
        pp[0] = acc0; pp[1] = acc1; pp[2] = acc2; pp[3] = acc3;
    }
    __syncthreads();
    if (kp == 0 && valid) {
        #pragma unroll
        for (int p = 0; p < 3; p++) {
            const u64* pp = (const u64*)&part[(p * 256 + (t & 255)) * 8];
            acc0 = add2(acc0, pp[0]);
            acc1 = add2(acc1, pp[1]);
            acc2 = add2(acc2, pp[2]);
            acc3 = add2(acc3, pp[3]);
        }
        float a[8];
        upk2(acc0, a[0], a[1]); upk2(acc1, a[2], a[3]);
        upk2(acc2, a[4], a[5]); upk2(acc3, a[6], a[7]);
        float bias2 = b2[o];
        int idx2 = o >> 1;
        if ((o & 1) == 0) {
            float base = base_filter[idx2];
            #pragma unroll
            for (int r = 0; r < 8; r++)
                g_filt[(long)(b0 + r) * HF + idx2] = base * (1.0f + a[r] + bias2);
        } else {
            float base = base_bias[idx2];
            #pragma unroll
            for (int r = 0; r < 8; r++)
                g_bias[(long)(b0 + r) * HF + idx2] = base + a[r] + bias2;
        }
    }
}

// ---------------- spectral kernel: 2 real columns per block via complex packing ----
// z = x_a + i x_b (d-pair shares head h -> same filter). Radix-4 (48 = 4x12), f32x2.
// 288 threads: e = t%12, c2 = (t/12)*2 (spatial col pair within 48x48 grid).
__global__ __launch_bounds__(288) void spectral_kernel() {
    __shared__ float sm[120 + 4 * 2496];
    float2* w12 = (float2*)sm;             // 12 entries
    float2* w48 = (float2*)(sm + 24);      // 48 entries
    float*  bufA = sm + 120;               // re plane (stride 48 -> 52)
    float*  Xim  = bufA + 2496;            // im plane
    float*  wre  = Xim + 2496;
    float*  wim  = wre + 2496;

    int blk = blockIdx.x;                  // 4096 = BB * 128
    int b = blk >> 7;
    int d0 = (blk & 127) * 2;
    int h = d0 >> 5;
    int t = threadIdx.x;
    int e  = t % 12;
    int c2 = (t / 12) * 2;
    const float inv48 = 1.0f / 48.0f;
    const u64 NEG1 = pk2(-1.0f, -1.0f);

    if (t < 12) w12[t] = g_tw[192 * t];
    else if (t < 60) w48[t - 12] = g_tw[48 * (t - 12)];
    const float* srcA = g_xh + ((long)b * DD + d0) * NN;
    const float* srcB = srcA + NN;
    for (int i = t; i < NN; i += 288) { bufA[i] = srcA[i]; Xim[i] = srcB[i]; }
    __syncthreads();

    float2 we1 = w48[e], we2 = w48[2 * e], we3 = w48[3 * e];
    u64 c1=pk2(we1.x,we1.x), s1=pk2(we1.y,we1.y), n1=pk2(-we1.y,-we1.y);
    u64 c2p=pk2(we2.x,we2.x), s2p=pk2(we2.y,we2.y), n2p=pk2(-we2.y,-we2.y);
    u64 c3=pk2(we3.x,we3.x), s3=pk2(we3.y,we3.y), n3=pk2(-we3.y,-we3.y);

    // ======== stage 1: forward over n1 (complex input), rows stride 48 ========
    {
        u64 S0r=0,S0i=0,S1r=0,S1i=0,S2r=0,S2i=0,S3r=0,S3i=0;
        int idx = 0;
        #pragma unroll
        for (int m = 0; m < 12; m++) {
            float2 w = w12[idx]; idx += e; if (idx >= 12) idx -= 12;
            u64 cc = pk2(w.x, w.x), ss = pk2(w.y, w.y), ns = pk2(-w.y, -w.y);
            u64 vr0 = *(const u64*)&bufA[(4*m+0)*48 + c2], vi0 = *(const u64*)&Xim[(4*m+0)*48 + c2];
            u64 vr1 = *(const u64*)&bufA[(4*m+1)*48 + c2], vi1 = *(const u64*)&Xim[(4*m+1)*48 + c2];
            u64 vr2 = *(const u64*)&bufA[(4*m+2)*48 + c2], vi2 = *(const u64*)&Xim[(4*m+2)*48 + c2];
            u64 vr3 = *(const u64*)&bufA[(4*m+3)*48 + c2], vi3 = *(const u64*)&Xim[(4*m+3)*48 + c2];
            S0r = f2fma(vr0, cc, S0r); S0r = f2fma(vi0, ss, S0r);
            S0i = f2fma(vi0, cc, S0i); S0i = f2fma(vr0, ns, S0i);
            S1r = f2fma(vr1, cc, S1r); S1r = f2fma(vi1, ss, S1r);
            S1i = f2fma(vi1, cc, S1i); S1i = f2fma(vr1, ns, S1i);
            S2r = f2fma(vr2, cc, S2r); S2r = f2fma(vi2, ss, S2r);
            S2i = f2fma(vi2, cc, S2i); S2i = f2fma(vr2, ns, S2i);
            S3r = f2fma(vr3, cc, S3r); S3r = f2fma(vi3, ss, S3r);
            S3i = f2fma(vi3, cc, S3i); S3i = f2fma(vr3, ns, S3i);
        }
        u64 T1r = f2fma(S1i, s1, mul2(S1r, c1)),  T1i = f2fma(S1r, n1, mul2(S1i, c1));
        u64 T2r = f2fma(S2i, s2p, mul2(S2r, c2p)), T2i = f2fma(S2r, n2p, mul2(S2i, c2p));
        u64 T3r = f2fma(S3i, s3, mul2(S3r, c3)),  T3i = f2fma(S3r, n3, mul2(S3i, c3));
        u64 ar = add2(S0r, T2r), ai = add2(S0i, T2i);
        u64 br = f2fma(T2r, NEG1, S0r), bi = f2fma(T2i, NEG1, S0i);
        u64 cr = add2(T1r, T3r), ci = add2(T1i, T3i);
        u64 dr = f2fma(T3r, NEG1, T1r), di = f2fma(T3i, NEG1, T1i);
        u64 Xr[4], Xi4[4];
        Xr[0] = add2(ar, cr);          Xi4[0] = add2(ai, ci);
        Xr[1] = add2(br, di);          Xi4[1] = f2fma(dr, NEG1, bi);
        Xr[2] = f2fma(cr, NEG1, ar);   Xi4[2] = f2fma(ci, NEG1, ai);
        Xr[3] = f2fma(di, NEG1, br);   Xi4[3] = add2(bi, dr);
        #pragma unroll
        for (int p = 0; p < 4; p++) {
            float r0, r1, i0, i1;
            upk2(Xr[p], r0, r1); upk2(Xi4[p], i0, i1);
            int k = e + 12 * p;
            float2 ta = g_tw[k * c2];
            wre[c2 * 52 + k]       = r0 * ta.x + i0 * ta.y;
            wim[c2 * 52 + k]       = i0 * ta.x - r0 * ta.y;
            float2 tb = g_tw[k * (c2 + 1)];
            wre[(c2 + 1) * 52 + k] = r1 * tb.x + i1 * tb.y;
            wim[(c2 + 1) * 52 + k] = i1 * tb.x - r1 * tb.y;
        }
    }
    __syncthreads();

    // ======== stage 2: forward over n2 (complex), rows stride 52; raw Z out ========
    {
        u64 S0r=0,S0i=0,S1r=0,S1i=0,S2r=0,S2i=0,S3r=0,S3i=0;
        int idx = 0;
        #pragma unroll
        for (int m = 0; m < 12; m++) {
            float2 w = w12[idx]; idx += e; if (idx >= 12) idx -= 12;
            u64 cc = pk2(w.x, w.x), ss = pk2(w.y, w.y), ns = pk2(-w.y, -w.y);
            u64 vr0 = *(const u64*)&wre[(4*m+0)*52 + c2], vi0 = *(const u64*)&wim[(4*m+0)*52 + c2];
            u64 vr1 = *(const u64*)&wre[(4*m+1)*52 + c2], vi1 = *(const u64*)&wim[(4*m+1)*52 + c2];
            u64 vr2 = *(const u64*)&wre[(4*m+2)*52 + c2], vi2 = *(const u64*)&wim[(4*m+2)*52 + c2];
            u64 vr3 = *(const u64*)&wre[(4*m+3)*52 + c2], vi3 = *(const u64*)&wim[(4*m+3)*52 + c2];
            S0r = f2fma(vr0, cc, S0r); S0r = f2fma(vi0, ss, S0r);
            S0i = f2fma(vi0, cc, S0i); S0i = f2fma(vr0, ns, S0i);
            S1r = f2fma(vr1, cc, S1r); S1r = f2fma(vi1, ss, S1r);
            S1i = f2fma(vi1, cc, S1i); S1i = f2fma(vr1, ns, S1i);
            S2r = f2fma(vr2, cc, S2r); S2r = f2fma(vi2, ss, S2r);
            S2i = f2fma(vi2, cc, S2i); S2i = f2fma(vr2, ns, S2i);
            S3r = f2fma(vr3, cc, S3r); S3r = f2fma(vi3, ss, S3r);
            S3i = f2fma(vi3, cc, S3i); S3i = f2fma(vr3, ns, S3i);
        }
        u64 T1r = f2fma(S1i, s1, mul2(S1r, c1)),  T1i = f2fma(S1r, n1, mul2(S1i, c1));
        u64 T2r = f2fma(S2i, s2p, mul2(S2r, c2p)), T2i = f2fma(S2r, n2p, mul2(S2i, c2p));
        u64 T3r = f2fma(S3i, s3, mul2(S3r, c3)),  T3i = f2fma(S3r, n3, mul2(S3i, c3));
        u64 ar = add2(S0r, T2r), ai = add2(S0i, T2i);
        u64 br = f2fma(T2r, NEG1, S0r), bi = f2fma(T2i, NEG1, S0i);
        u64 cr = add2(T1r, T3r), ci = add2(T1i, T3i);
        u64 dr = f2fma(T3r, NEG1, T1r), di = f2fma(T3i, NEG1, T1i);
        // write raw Z (rows k2 = e+12p, cols k1 = c2 pair) into bufA/Xim
        *(u64*)&bufA[(e     ) * 52 + c2] = add2(ar, cr);
        *(u64*)&Xim [(e     ) * 52 + c2] = add2(ai, ci);
        *(u64*)&bufA[(e + 12) * 52 + c2] = add2(br, di);
        *(u64*)&Xim [(e + 12) * 52 + c2] = f2fma(dr, NEG1, bi);
        *(u64*)&bufA[(e + 24) * 52 + c2] = f2fma(cr, NEG1, ar);
        *(u64*)&Xim [(e + 24) * 52 + c2] = f2fma(ci, NEG1, ai);
        *(u64*)&bufA[(e + 36) * 52 + c2] = f2fma(di, NEG1, br);
        *(u64*)&Xim [(e + 36) * 52 + c2] = add2(bi, dr);
    }
    __syncthreads();

    // ======== mid-pass: Hermitian split, modulate (k <= 1152), repack ========
    {
        const float* fB = g_filt + (long)b * HF + (long)h * FB;
        const float* cB = g_bias + (long)b * HF + (long)h * FB;
        const float sc = 0.5f * inv48;
        for (int k = t; k <= 1152; k += 288) {
            int a = k / 48, bq = k - a * 48;
            int a2, b2q;
            if (bq == 0) { a2 = (48 - a) % 48; b2q = 0; }
            else         { a2 = 47 - a;        b2q = 48 - bq; }
            int i1 = a * 52 + bq, i2 = a2 * 52 + b2q;
            float Zr = bufA[i1], Zi = Xim[i1];
            float Mr = bufA[i2], Mi = Xim[i2];
            float Ar = (Zr + Mr) * sc, Ai = (Zi - Mi) * sc;
            float Br = (Zi + Mi) * sc, Bi = (Mr - Zr) * sc;
            float g = fB[k], cc = cB[k];
            // modulate A
            float mr = Ar * g + cc, mi = Ai * g;
            float mag = sqrtf(mr * mr + mi * mi);
            float fac = 0.5f * mag * (1.0f + erff(mag * 0.70710678118654752f))
                        * __fdividef(1.0f, mag + 1e-6f);
            float TAr = mr * fac, TAi = mi * fac;
            // modulate B
            mr = Br * g + cc; mi = Bi * g;
            mag = sqrtf(mr * mr + mi * mi);
            fac = 0.5f * mag * (1.0f + erff(mag * 0.70710678118654752f))
                  * __fdividef(1.0f, mag + 1e-6f);
            float TBr = mr * fac, TBi = mi * fac;
            // z~_k = A~ + i B~ ;  z~_{N-k} = conj(A~) + i conj(B~)
            bufA[i1] = TAr - TBi;  Xim[i1] = TAi + TBr;
            bufA[i2] = TAr + TBi;  Xim[i2] = TBr - TAi;
        }
    }
    __syncthreads();

    // ======== stage 3: inverse over k2 (complex), rows stride 52 ========
    {
        u64 S0r=0,S0i=0,S1r=0,S1i=0,S2r=0,S2i=0,S3r=0,S3i=0;
        int idx = 0;
        #pragma unroll
        for (int m = 0; m < 12; m++) {
            float2 w = w12[idx]; idx += e; if (idx >= 12) idx -= 12;
            u64 cc = pk2(w.x, w.x), ss = pk2(w.y, w.y), ns = pk2(-w.y, -w.y);
            u64 vr0 = *(const u64*)&bufA[(4*m+0)*52 + c2], vi0 = *(const u64*)&Xim[(4*m+0)*52 + c2];
            u64 vr1 = *(const u64*)&bufA[(4*m+1)*52 + c2], vi1 = *(const u64*)&Xim[(4*m+1)*52 + c2];
            u64 vr2 = *(const u64*)&bufA[(4*m+2)*52 + c2], vi2 = *(const u64*)&Xim[(4*m+2)*52 + c2];
            u64 vr3 = *(const u64*)&bufA[(4*m+3)*52 + c2], vi3 = *(const u64*)&Xim[(4*m+3)*52 + c2];
            S0r = f2fma(vr0, cc, S0r); S0r = f2fma(vi0, ns, S0r);
            S0i = f2fma(vi0, cc, S0i); S0i = f2fma(vr0, ss, S0i);
            S1r = f2fma(vr1, cc, S1r); S1r = f2fma(vi1, ns, S1r);
            S1i = f2fma(vi1, cc, S1i); S1i = f2fma(vr1, ss, S1i);
            S2r = f2fma(vr2, cc, S2r); S2r = f2fma(vi2, ns, S2r);
            S2i = f2fma(vi2, cc, S2i); S2i = f2fma(vr2, ss, S2i);
            S3r = f2fma(vr3, cc, S3r); S3r = f2fma(vi3, ns, S3r);
            S3i = f2fma(vi3, cc, S3i); S3i = f2fma(vr3, ss, S3i);
        }
        u64 T1r = f2fma(S1i, n1, mul2(S1r, c1)),  T1i = f2fma(S1r, s1, mul2(S1i, c1));
        u64 T2r = f2fma(S2i, n2p, mul2(S2r, c2p)), T2i = f2fma(S2r, s2p, mul2(S2i, c2p));
        u64 T3r = f2fma(S3i, n3, mul2(S3r, c3)),  T3i = f2fma(S3r, s3, mul2(S3i, c3));
        u64 ar = add2(S0r, T2r), ai = add2(S0i, T2i);
        u64 br = f2fma(T2r, NEG1, S0r), bi = f2fma(T2i, NEG1, S0i);
        u64 cr = add2(T1r, T3r), ci = add2(T1i, T3i);
        u64 dr = f2fma(T3r, NEG1, T1r), di = f2fma(T3i, NEG1, T1i);
        u64 Xr[4], Xi4[4];
        Xr[0] = add2(ar, cr);          Xi4[0] = add2(ai, ci);
        Xr[1] = f2fma(di, NEG1, br);   Xi4[1] = add2(bi, dr);          // b + i d
        Xr[2] = f2fma(cr, NEG1, ar);   Xi4[2] = f2fma(ci, NEG1, ai);
        Xr[3] = add2(br, di);          Xi4[3] = f2fma(dr, NEG1, bi);   // b - i d
        #pragma unroll
        for (int p = 0; p < 4; p++) {
            float r0, r1, i0, i1;
            upk2(Xr[p], r0, r1); upk2(Xi4[p], i0, i1);
            int r = e + 12 * p;
            float2 ta = g_tw[r * c2];
            wre[c2 * 52 + r]       = r0 * ta.x - i0 * ta.y;
            wim[c2 * 52 + r]       = r0 * ta.y + i0 * ta.x;
            float2 tb = g_tw[r * (c2 + 1)];
            wre[(c2 + 1) * 52 + r] = r1 * tb.x - i1 * tb.y;
            wim[(c2 + 1) * 52 + r] = r1 * tb.y + i1 * tb.x;
        }
    }
    __syncthreads();

    // ======== stage 4: inverse over k1 (full complex out: re->colA, im->colB) ========
    {
        u64 S0r=0,S0i=0,S1r=0,S1i=0,S2r=0,S2i=0,S3r=0,S3i=0;
        int idx = 0;
        #pragma unroll
        for (int m = 0; m < 12; m++) {
            float2 w = w12[idx]; idx += e; if (idx >= 12) idx -= 12;
            u64 cc = pk2(w.x, w.x), ss = pk2(w.y, w.y), ns = pk2(-w.y, -w.y);
            u64 vr0 = *(const u64*)&wre[(4*m+0)*52 + c2], vi0 = *(const u64*)&wim[(4*m+0)*52 + c2];
            u64 vr1 = *(const u64*)&wre[(4*m+1)*52 + c2], vi1 = *(const u64*)&wim[(4*m+1)*52 + c2];
            u64 vr2 = *(const u64*)&wre[(4*m+2)*52 + c2], vi2 = *(const u64*)&wim[(4*m+2)*52 + c2];
            u64 vr3 = *(const u64*)&wre[(4*m+3)*52 + c2], vi3 = *(const u64*)&wim[(4*m+3)*52 + c2];
            S0r = f2fma(vr0, cc, S0r); S0r = f2fma(vi0, ns, S0r);
            S0i = f2fma(vi0, cc, S0i); S0i = f2fma(vr0, ss, S0i);
            S1r = f2fma(vr1, cc, S1r); S1r = f2fma(vi1, ns, S1r);
            S1i = f2fma(vi1, cc, S1i); S1i = f2fma(vr1, ss, S1i);
            S2r = f2fma(vr2, cc, S2r); S2r = f2fma(vi2, ns, S2r);
            S2i = f2fma(vi2, cc, S2i); S2i = f2fma(vr2, ss, S2i);
            S3r = f2fma(vr3, cc, S3r); S3r = f2fma(vi3, ns, S3r);
            S3i = f2fma(vi3, cc, S3i); S3i = f2fma(vr3, ss, S3i);
        }
        u64 T1r = f2fma(S1i, n1, mul2(S1r, c1)),  T1i = f2fma(S1r, s1, mul2(S1i, c1));
        u64 T2r = f2fma(S2i, n2p, mul2(S2r, c2p)), T2i = f2fma(S2r, s2p, mul2(S2i, c2p));
        u64 T3r = f2fma(S3i, n3, mul2(S3r, c3)),  T3i = f2fma(S3r, s3, mul2(S3i, c3));
        u64 ar = add2(S0r, T2r), ai = add2(S0i, T2i);
        u64 br = f2fma(T2r, NEG1, S0r), bi = f2fma(T2i, NEG1, S0i);
        u64 cr = add2(T1r, T3r), ci = add2(T1i, T3i);
        u64 dr = f2fma(T3r, NEG1, T1r), di = f2fma(T3i, NEG1, T1i);
        u64 I48 = pk2(inv48, inv48);
        float* dstA = g_yt + ((long)b * DD + d0) * NN;
        float* dstB = dstA + NN;
        u64 Xr, Xi;
        Xr = add2(ar, cr);          Xi = add2(ai, ci);
        *(u64*)&dstA[(e     ) * 48 + c2] = mul2(Xr, I48);
        *(u64*)&dstB[(e     ) * 48 + c2] = mul2(Xi, I48);
        Xr = f2fma(di, NEG1, br);   Xi = add2(bi, dr);
        *(u64*)&dstA[(e + 12) * 48 + c2] = mul2(Xr, I48);
        *(u64*)&dstB[(e + 12) * 48 + c2] = mul2(Xi, I48);
        Xr = f2fma(cr, NEG1, ar);   Xi = f2fma(ci, NEG1, ai);
        *(u64*)&dstA[(e + 24) * 48 + c2] = mul2(Xr, I48);
        *(u64*)&dstB[(e + 24) * 48 + c2] = mul2(Xi, I48);
        Xr = add2(br, di);          Xi = f2fma(dr, NEG1, bi);
        *(u64*)&dstA[(e + 36) * 48 + c2] = mul2(Xr, I48);
        *(u64*)&dstB[(e + 36) * 48 + c2] = mul2(Xi, I48);
    }
}

// ---------------- output: out[b][n][d] = x + yt^T ----------------
__global__ void addout_kernel(const float* __restrict__ x, float* __restrict__ out) {
    __shared__ float tile[32][33];
    int b  = blockIdx.z;
    int n0 = blockIdx.x * 32;
    int d0 = blockIdx.y * 32;
    int tx = threadIdx.x, ty = threadIdx.y;
    const float* src = g_yt + ((long)b * DD + d0) * NN + n0;
    #pragma unroll
    for (int i = 0; i < 32; i += 8)
        tile[ty + i][tx] = src[(long)(ty + i) * NN + tx];
    __syncthreads();
    long base = ((long)b * NN + n0) * DD + d0;
    #pragma unroll
    for (int i = 0; i < 32; i += 8)
        out[base + (long)(ty + i) * DD + tx] =
            x[base + (long)(ty + i) * DD + tx] + tile[tx][ty + i];
}

// ---------------- launch ----------------
extern "C" void kernel_launch(void* const* d_in, const int* in_sizes, int n_in,
                              void* d_out, int out_size) {
    const float* x           = (const float*)d_in[0];
    const float* base_filter = (const float*)d_in[1];
    const float* base_bias   = (const float*)d_in[2];
    const float* ln_gamma    = (const float*)d_in[3];
    const float* ln_beta     = (const float*)d_in[4];
    const float* W1          = (const float*)d_in[5];
    const float* b1          = (const float*)d_in[6];
    const float* W2          = (const float*)d_in[7];
    const float* b2          = (const float*)d_in[8];
    float* out = (float*)d_out;

    static bool attr_done = false;
    if (!attr_done) {
        cudaFuncSetAttribute(mlp2_kernel,
                             cudaFuncAttributeMaxDynamicSharedMemorySize, MLP2_SMEM);
        attr_done = true;
    }

    init_kernel<<<32, 256>>>();
    ln_t_kernel<<<dim3(NN / 32, BB), 256>>>(x, ln_gamma, ln_beta);
    mlp1_kernel<<<dim3(BB, 4), 512>>>(W1, b1);
    mlp2_kernel<<<(OUT2 + 63) / 64, 1024, MLP2_SMEM>>>(W2, b2, base_filter, base_bias);
    spectral_kernel<<<BB * DD / 2, 288>>>();
    addout_kernel<<<dim3(NN / 32, DD / 32, BB), dim3(32, 8)>>>(x, out);
}